// round 3
// baseline (speedup 1.0000x reference)
#include <cuda_runtime.h>
#include <cuda_bf16.h>
#include <stdint.h>

// Problem constants (from reference setup_inputs)
#define N_NODES 50000
#define C_IN    1536
#define C_HID   256
#define C_OUT   128

// Scratch (device globals, float4 for guaranteed 16B alignment).
__device__ float4 g_h1  [N_NODES * C_HID / 4];  // x@W1, later relu(agg1+b1)
__device__ float4 g_agg1[N_NODES * C_HID / 4];  // aggregated layer1
__device__ float4 g_h2  [N_NODES * C_OUT / 4];  // z@W2
__device__ float4 g_agg2[N_NODES * C_OUT / 4];  // aggregated layer2
__device__ float  g_dinv[N_NODES];              // deg accumulator -> 1/sqrt(deg)

// ---------------------------------------------------------------------------
// degree / dinv
// ---------------------------------------------------------------------------
__global__ void init_deg_kernel() {
    int i = blockIdx.x * blockDim.x + threadIdx.x;
    if (i < N_NODES) g_dinv[i] = 1.0f;   // self-loop contributes 1
}

__global__ void deg_accum_kernel(const int* __restrict__ dst, int E) {
    int i = blockIdx.x * blockDim.x + threadIdx.x;
    if (i < E) {
        unsigned d = (unsigned)dst[i];
        if (d < N_NODES) atomicAdd(&g_dinv[d], 1.0f);
    }
}

__global__ void dinv_finalize_kernel() {
    int i = blockIdx.x * blockDim.x + threadIdx.x;
    if (i < N_NODES) g_dinv[i] = rsqrtf(g_dinv[i]);
}

// ---------------------------------------------------------------------------
// SGEMM: C[M,N] = A[M,K] @ B[K,N], fp32, tile 128x64, thread-tile 8x4.
// mode 0: A = x (param),        C = g_h1  (K=1536, N=256)
// mode 1: A = g_h1 (post-relu), C = g_h2  (K=256,  N=128)
// ---------------------------------------------------------------------------
__global__ __launch_bounds__(256) void sgemm128x64(
    const float* __restrict__ Aparam, const float* __restrict__ B,
    int M, int K, int N, int mode)
{
    __shared__ __align__(16) float  As[128][16];
    __shared__ __align__(16) float4 Bs[16][16];     // 16 rows x 64 floats

    const float* A = (mode == 0) ? Aparam : (const float*)g_h1;
    float*       C = (mode == 0) ? (float*)g_h1 : (float*)g_h2;

    const int tid = threadIdx.x;
    const int tx = tid & 15;          // 0..15, col group
    const int ty = tid >> 4;          // 0..15, row group
    const int rowBase = blockIdx.x * 128;
    const int colBase = blockIdx.y * 64;

    const int aRow0 = tid >> 2;        // 0..63
    const int aCol  = (tid & 3) * 4;   // 0,4,8,12
    const int bRow  = tid >> 4;        // 0..15
    const int bCol4 = tid & 15;

    float acc[8][4];
#pragma unroll
    for (int i = 0; i < 8; ++i)
#pragma unroll
        for (int j = 0; j < 4; ++j) acc[i][j] = 0.0f;

    for (int k0 = 0; k0 < K; k0 += 16) {
#pragma unroll
        for (int h = 0; h < 2; ++h) {
            int ar = aRow0 + h * 64;
            int gr = rowBase + ar;
            float4 v = make_float4(0.f, 0.f, 0.f, 0.f);
            if (gr < M) v = *(const float4*)(A + (size_t)gr * K + k0 + aCol);
            *(float4*)&As[ar][aCol] = v;
        }
        Bs[bRow][bCol4] = *(const float4*)(B + (size_t)(k0 + bRow) * N + colBase + bCol4 * 4);
        __syncthreads();

#pragma unroll
        for (int kk = 0; kk < 16; ++kk) {
            float4 b = Bs[kk][tx];
#pragma unroll
            for (int i = 0; i < 8; ++i) {
                float a = As[ty * 8 + i][kk];
                acc[i][0] += a * b.x;
                acc[i][1] += a * b.y;
                acc[i][2] += a * b.z;
                acc[i][3] += a * b.w;
            }
        }
        __syncthreads();
    }

#pragma unroll
    for (int i = 0; i < 8; ++i) {
        int row = rowBase + ty * 8 + i;
        if (row < M) {
            float4 v = make_float4(acc[i][0], acc[i][1], acc[i][2], acc[i][3]);
            *(float4*)(C + (size_t)row * N + colBase + tx * 4) = v;
        }
    }
}

// ---------------------------------------------------------------------------
// Self-loop init: agg[i][c] = h[i][c] * dinv[i]^2   (vectorized float4)
// layer 0: g_h1 -> g_agg1 (C4=64); layer 1: g_h2 -> g_agg2 (C4=32)
// ---------------------------------------------------------------------------
__global__ void selfloop_init_kernel(int C4, int layer) {
    const float4* h   = (layer == 0) ? g_h1   : g_h2;
    float4*       agg = (layer == 0) ? g_agg1 : g_agg2;
    int idx = blockIdx.x * blockDim.x + threadIdx.x;
    int total = N_NODES * C4;
    if (idx >= total) return;
    int row = idx / C4;
    float w = g_dinv[row];
    w = w * w;
    float4 v = h[idx];
    v.x *= w; v.y *= w; v.z *= w; v.w *= w;
    agg[idx] = v;
}

// ---------------------------------------------------------------------------
// Edge scatter: one warp per edge. agg[dst] += h[src] * dinv[src]*dinv[dst]
// Scalar atomicAdd -> REDG.E.ADD.F32 (return value unused).
// ---------------------------------------------------------------------------
__global__ __launch_bounds__(256) void scatter_edges_kernel(
    const int* __restrict__ src, const int* __restrict__ dst,
    int E, int C4, int layer)
{
    const float4* h   = (layer == 0) ? g_h1 : g_h2;
    float*        agg = (layer == 0) ? (float*)g_agg1 : (float*)g_agg2;

    int warpId = (blockIdx.x * blockDim.x + threadIdx.x) >> 5;
    int lane = threadIdx.x & 31;
    if (warpId >= E) return;
    unsigned s = (unsigned)src[warpId];
    unsigned d = (unsigned)dst[warpId];
    if (s >= N_NODES || d >= N_NODES) return;   // dtype-safety guard
    float w = g_dinv[s] * g_dinv[d];
    const float4* hp = h + (size_t)s * C4;
    float*        ap = agg + (size_t)d * C4 * 4;
#pragma unroll 2
    for (int j = lane; j < C4; j += 32) {
        float4 v = __ldg(hp + j);
        float* p = ap + j * 4;
        atomicAdd(p + 0, v.x * w);
        atomicAdd(p + 1, v.y * w);
        atomicAdd(p + 2, v.z * w);
        atomicAdd(p + 3, v.w * w);
    }
}

// ---------------------------------------------------------------------------
// g_h1 = relu(g_agg1 + b1), vectorized (C4 = 64)
// ---------------------------------------------------------------------------
__global__ void bias_relu_kernel(const float* __restrict__ b, int C4) {
    int idx = blockIdx.x * blockDim.x + threadIdx.x;
    int total = N_NODES * C4;
    if (idx >= total) return;
    int c4 = idx % C4;
    float4 v = g_agg1[idx];
    float4 bb = ((const float4*)b)[c4];
    v.x = fmaxf(v.x + bb.x, 0.f);
    v.y = fmaxf(v.y + bb.y, 0.f);
    v.z = fmaxf(v.z + bb.z, 0.f);
    v.w = fmaxf(v.w + bb.w, 0.f);
    g_h1[idx] = v;
}

// ---------------------------------------------------------------------------
// out = normalize(g_agg2 + b2) rows of 128 — one warp per row, 1 float4/lane.
// ---------------------------------------------------------------------------
__global__ __launch_bounds__(256) void final_normalize_kernel(
    const float* __restrict__ b, float* __restrict__ out)
{
    int warpId = (blockIdx.x * blockDim.x + threadIdx.x) >> 5;
    int lane = threadIdx.x & 31;
    if (warpId >= N_NODES) return;
    float4 v = g_agg2[(size_t)warpId * 32 + lane];
    float4 bb = ((const float4*)b)[lane];
    v.x += bb.x; v.y += bb.y; v.z += bb.z; v.w += bb.w;
    float s = v.x * v.x + v.y * v.y + v.z * v.z + v.w * v.w;
#pragma unroll
    for (int m = 16; m > 0; m >>= 1) s += __shfl_xor_sync(0xffffffffu, s, m);
    float nrm = sqrtf(s);
    float inv = 1.0f / fmaxf(nrm, 1e-12f);
    v.x *= inv; v.y *= inv; v.z *= inv; v.w *= inv;
    ((float4*)out)[(size_t)warpId * 32 + lane] = v;
}

// ---------------------------------------------------------------------------
// Launch
// ---------------------------------------------------------------------------
extern "C" void kernel_launch(void* const* d_in, const int* in_sizes, int n_in,
                              void* d_out, int out_size) {
    const float* x  = (const float*)d_in[0];
    const int*   ei = (const int*)d_in[1];      // int32 (JAX x64-disabled downcast)
    const float* W1 = (const float*)d_in[2];
    const float* b1 = (const float*)d_in[3];
    const float* W2 = (const float*)d_in[4];
    const float* b2 = (const float*)d_in[5];
    float* out = (float*)d_out;

    const int E = in_sizes[1] / 2;
    const int* src = ei;
    const int* dst = ei + E;

    // 1) degrees -> dinv
    init_deg_kernel<<<(N_NODES + 255) / 256, 256>>>();
    deg_accum_kernel<<<(E + 255) / 256, 256>>>(dst, E);
    dinv_finalize_kernel<<<(N_NODES + 255) / 256, 256>>>();

    // 2) g_h1 = x @ W1
    {
        dim3 grid((N_NODES + 127) / 128, C_HID / 64);
        sgemm128x64<<<grid, 256>>>(x, W1, N_NODES, C_IN, C_HID, 0);
    }

    // 3) aggregation layer 1
    {
        int C4 = C_HID / 4;
        int total = N_NODES * C4;
        selfloop_init_kernel<<<(total + 255) / 256, 256>>>(C4, 0);
        int wpb = 256 / 32;
        scatter_edges_kernel<<<(E + wpb - 1) / wpb, 256>>>(src, dst, E, C4, 0);
    }

    // 4) g_h1 = relu(g_agg1 + b1)
    {
        int C4 = C_HID / 4;
        int total = N_NODES * C4;
        bias_relu_kernel<<<(total + 255) / 256, 256>>>(b1, C4);
    }

    // 5) g_h2 = g_h1 @ W2
    {
        dim3 grid((N_NODES + 127) / 128, C_OUT / 64);
        sgemm128x64<<<grid, 256>>>(nullptr, W2, N_NODES, C_HID, C_OUT, 1);
    }

    // 6) aggregation layer 2
    {
        int C4 = C_OUT / 4;
        int total = N_NODES * C4;
        selfloop_init_kernel<<<(total + 255) / 256, 256>>>(C4, 1);
        int wpb = 256 / 32;
        scatter_edges_kernel<<<(E + wpb - 1) / wpb, 256>>>(src, dst, E, C4, 1);
    }

    // 7) out = normalize(g_agg2 + b2)
    {
        int wpb = 256 / 32;
        final_normalize_kernel<<<(N_NODES + wpb - 1) / wpb, 256>>>(b2, out);
    }
}

// round 4
// speedup vs baseline: 1.8711x; 1.8711x over previous
#include <cuda_runtime.h>
#include <cuda_bf16.h>
#include <stdint.h>

// Problem constants (from reference setup_inputs)
#define N_NODES 50000
#define C_IN    1536
#define C_HID   256
#define C_OUT   128

// Scratch (device globals, float4 for guaranteed 16B alignment).
__device__ float4 g_h1  [N_NODES * C_HID / 4];  // x@W1, later relu(agg1+b1)
__device__ float4 g_agg1[N_NODES * C_HID / 4];  // aggregated layer1
__device__ float4 g_h2  [N_NODES * C_OUT / 4];  // z@W2
__device__ float4 g_agg2[N_NODES * C_OUT / 4];  // aggregated layer2
__device__ float  g_dinv[N_NODES];              // deg accumulator -> 1/sqrt(deg)

// ---------------------------------------------------------------------------
// degree / dinv
// ---------------------------------------------------------------------------
__global__ void init_deg_kernel() {
    int i = blockIdx.x * blockDim.x + threadIdx.x;
    if (i < N_NODES) g_dinv[i] = 1.0f;   // self-loop contributes 1
}

__global__ void deg_accum_kernel(const int* __restrict__ dst, int E) {
    int i = blockIdx.x * blockDim.x + threadIdx.x;
    if (i < E) {
        unsigned d = (unsigned)dst[i];
        if (d < N_NODES) atomicAdd(&g_dinv[d], 1.0f);
    }
}

__global__ void dinv_finalize_kernel() {
    int i = blockIdx.x * blockDim.x + threadIdx.x;
    if (i < N_NODES) g_dinv[i] = rsqrtf(g_dinv[i]);
}

// ---------------------------------------------------------------------------
// Tensor-core GEMM: C[M,N] = A[M,K] @ B[K,N], fp32 in/out.
// bf16 2-term split: A = Ah + Al, B = Bh + Bl; C += Ah*Bh + Ah*Bl + Al*Bh.
// Tile: BM=128, BN=128, BK=32. 8 warps: 2 (M) x 4 (N); warp tile 64x32.
// mma.sync.m16n8k16.bf16 (row.col), fp32 accumulate.
// mode 0: A = x (param, K=1536), C = g_h1
// mode 1: A = g_h1 (K=256),      C = g_h2
// ---------------------------------------------------------------------------
#define BKP 36   // padded k-stride (elements) -> 72B rows, conflict-free frags

__device__ __forceinline__ void mma_bf16(float c[4], const uint32_t a[4],
                                         const uint32_t b[2]) {
    asm volatile(
        "mma.sync.aligned.m16n8k16.row.col.f32.bf16.bf16.f32 "
        "{%0,%1,%2,%3}, {%4,%5,%6,%7}, {%8,%9}, {%0,%1,%2,%3};\n"
        : "+f"(c[0]), "+f"(c[1]), "+f"(c[2]), "+f"(c[3])
        : "r"(a[0]), "r"(a[1]), "r"(a[2]), "r"(a[3]), "r"(b[0]), "r"(b[1]));
}

__global__ __launch_bounds__(256) void mma_gemm(
    const float* __restrict__ Aparam, const float* __restrict__ B,
    int M, int K, int mode)
{
    __shared__ __align__(16) __nv_bfloat16 As_hi[128][BKP];
    __shared__ __align__(16) __nv_bfloat16 As_lo[128][BKP];
    __shared__ __align__(16) __nv_bfloat16 Bs_hi[128][BKP];  // [n][k]
    __shared__ __align__(16) __nv_bfloat16 Bs_lo[128][BKP];

    const float* A = (mode == 0) ? Aparam : (const float*)g_h1;
    float*       C = (mode == 0) ? (float*)g_h1 : (float*)g_h2;
    const int    N = (mode == 0) ? C_HID : C_OUT;

    const int tid  = threadIdx.x;
    const int lane = tid & 31;
    const int warp = tid >> 5;
    const int warpM = warp & 1;        // 0..1 -> 64 rows each
    const int warpN = warp >> 1;       // 0..3 -> 32 cols each
    const int g   = lane >> 2;         // groupID 0..7
    const int t4  = lane & 3;          // threadID_in_group

    const int rowBase = blockIdx.x * 128;
    const int colBase = blockIdx.y * 128;

    float acc[4][4][4];                // [mi][ni][reg]
#pragma unroll
    for (int mi = 0; mi < 4; ++mi)
#pragma unroll
        for (int ni = 0; ni < 4; ++ni)
#pragma unroll
            for (int r = 0; r < 4; ++r) acc[mi][ni][r] = 0.0f;

    for (int k0 = 0; k0 < K; k0 += 32) {
        // ---- stage A tile (128x32 f32 -> hi/lo bf16, [m][k]) ----
#pragma unroll
        for (int i = 0; i < 4; ++i) {
            int idx = tid + i * 256;          // 0..1023
            int r   = idx >> 3;               // 0..127
            int c4  = (idx & 7) * 4;          // 0,4,...,28
            int gr  = rowBase + r;
            float4 v = make_float4(0.f, 0.f, 0.f, 0.f);
            if (gr < M) v = *(const float4*)(A + (size_t)gr * K + k0 + c4);
            float va[4] = {v.x, v.y, v.z, v.w};
#pragma unroll
            for (int j = 0; j < 2; ++j) {
                __nv_bfloat162 h2, l2;
                float f0 = va[j * 2], f1 = va[j * 2 + 1];
                __nv_bfloat16 h0 = __float2bfloat16_rn(f0);
                __nv_bfloat16 h1 = __float2bfloat16_rn(f1);
                h2 = __nv_bfloat162(h0, h1);
                l2 = __nv_bfloat162(__float2bfloat16_rn(f0 - __bfloat162float(h0)),
                                    __float2bfloat16_rn(f1 - __bfloat162float(h1)));
                *(__nv_bfloat162*)&As_hi[r][c4 + j * 2] = h2;
                *(__nv_bfloat162*)&As_lo[r][c4 + j * 2] = l2;
            }
        }
        // ---- stage B tile (32x128 f32 -> hi/lo bf16, transposed [n][k]) ----
#pragma unroll
        for (int i = 0; i < 4; ++i) {
            int idx = tid + i * 256;          // 0..1023
            int r   = idx >> 5;               // k row 0..31
            int c4  = (idx & 31) * 4;         // n col 0..124
            float4 v = *(const float4*)(B + (size_t)(k0 + r) * N + colBase + c4);
            float va[4] = {v.x, v.y, v.z, v.w};
#pragma unroll
            for (int j = 0; j < 4; ++j) {
                __nv_bfloat16 h = __float2bfloat16_rn(va[j]);
                Bs_hi[c4 + j][r] = h;
                Bs_lo[c4 + j][r] = __float2bfloat16_rn(va[j] - __bfloat162float(h));
            }
        }
        __syncthreads();

        // ---- compute: two k16 sub-steps ----
#pragma unroll
        for (int ks = 0; ks < 32; ks += 16) {
            uint32_t ah[4][4], al[4][4];
#pragma unroll
            for (int mi = 0; mi < 4; ++mi) {
                int mrow = warpM * 64 + mi * 16 + g;
#pragma unroll
                for (int r = 0; r < 4; ++r) {
                    int row = mrow + (r & 1) * 8;
                    int col = ks + t4 * 2 + (r >> 1) * 8;
                    ah[mi][r] = *(const uint32_t*)&As_hi[row][col];
                    al[mi][r] = *(const uint32_t*)&As_lo[row][col];
                }
            }
            uint32_t bh[4][2], bl[4][2];
#pragma unroll
            for (int ni = 0; ni < 4; ++ni) {
                int nrow = warpN * 32 + ni * 8 + g;
#pragma unroll
                for (int r = 0; r < 2; ++r) {
                    int col = ks + t4 * 2 + r * 8;
                    bh[ni][r] = *(const uint32_t*)&Bs_hi[nrow][col];
                    bl[ni][r] = *(const uint32_t*)&Bs_lo[nrow][col];
                }
            }
#pragma unroll
            for (int mi = 0; mi < 4; ++mi)
#pragma unroll
                for (int ni = 0; ni < 4; ++ni) {
                    mma_bf16(acc[mi][ni], ah[mi], bh[ni]);
                    mma_bf16(acc[mi][ni], ah[mi], bl[ni]);
                    mma_bf16(acc[mi][ni], al[mi], bh[ni]);
                }
        }
        __syncthreads();
    }

    // ---- epilogue ----
#pragma unroll
    for (int mi = 0; mi < 4; ++mi) {
#pragma unroll
        for (int ni = 0; ni < 4; ++ni) {
            int col = colBase + warpN * 32 + ni * 8 + t4 * 2;
            int r0  = rowBase + warpM * 64 + mi * 16 + g;
            if (r0 < M)
                *(float2*)(C + (size_t)r0 * N + col) =
                    make_float2(acc[mi][ni][0], acc[mi][ni][1]);
            int r1 = r0 + 8;
            if (r1 < M)
                *(float2*)(C + (size_t)r1 * N + col) =
                    make_float2(acc[mi][ni][2], acc[mi][ni][3]);
        }
    }
}

// ---------------------------------------------------------------------------
// Self-loop init: agg[i][c] = h[i][c] * dinv[i]^2   (vectorized float4)
// ---------------------------------------------------------------------------
__global__ void selfloop_init_kernel(int C4, int layer) {
    const float4* h   = (layer == 0) ? g_h1   : g_h2;
    float4*       agg = (layer == 0) ? g_agg1 : g_agg2;
    int idx = blockIdx.x * blockDim.x + threadIdx.x;
    int total = N_NODES * C4;
    if (idx >= total) return;
    int row = idx / C4;
    float w = g_dinv[row];
    w = w * w;
    float4 v = h[idx];
    v.x *= w; v.y *= w; v.z *= w; v.w *= w;
    agg[idx] = v;
}

// ---------------------------------------------------------------------------
// Edge scatter: one warp per edge. agg[dst] += h[src] * dinv[src]*dinv[dst]
// Vector fp32 reduction (red.global.add.v4.f32): 4x fewer red ops.
// ---------------------------------------------------------------------------
__device__ __forceinline__ void red_add_v4(float* p, float4 v) {
    asm volatile("red.global.add.v4.f32 [%0], {%1, %2, %3, %4};"
                 :: "l"(p), "f"(v.x), "f"(v.y), "f"(v.z), "f"(v.w)
                 : "memory");
}

__global__ __launch_bounds__(256) void scatter_edges_kernel(
    const int* __restrict__ src, const int* __restrict__ dst,
    int E, int C4, int layer)
{
    const float4* h   = (layer == 0) ? g_h1 : g_h2;
    float*        agg = (layer == 0) ? (float*)g_agg1 : (float*)g_agg2;

    int warpId = (blockIdx.x * blockDim.x + threadIdx.x) >> 5;
    int lane = threadIdx.x & 31;
    if (warpId >= E) return;
    unsigned s = (unsigned)src[warpId];
    unsigned d = (unsigned)dst[warpId];
    if (s >= N_NODES || d >= N_NODES) return;   // dtype-safety guard
    float w = g_dinv[s] * g_dinv[d];
    const float4* hp = h + (size_t)s * C4;
    float*        ap = agg + (size_t)d * C4 * 4;
#pragma unroll 2
    for (int j = lane; j < C4; j += 32) {
        float4 v = __ldg(hp + j);
        v.x *= w; v.y *= w; v.z *= w; v.w *= w;
        red_add_v4(ap + j * 4, v);
    }
}

// ---------------------------------------------------------------------------
// g_h1 = relu(g_agg1 + b1), vectorized (C4 = 64)
// ---------------------------------------------------------------------------
__global__ void bias_relu_kernel(const float* __restrict__ b, int C4) {
    int idx = blockIdx.x * blockDim.x + threadIdx.x;
    int total = N_NODES * C4;
    if (idx >= total) return;
    int c4 = idx % C4;
    float4 v = g_agg1[idx];
    float4 bb = ((const float4*)b)[c4];
    v.x = fmaxf(v.x + bb.x, 0.f);
    v.y = fmaxf(v.y + bb.y, 0.f);
    v.z = fmaxf(v.z + bb.z, 0.f);
    v.w = fmaxf(v.w + bb.w, 0.f);
    g_h1[idx] = v;
}

// ---------------------------------------------------------------------------
// out = normalize(g_agg2 + b2) rows of 128 — one warp per row, 1 float4/lane.
// ---------------------------------------------------------------------------
__global__ __launch_bounds__(256) void final_normalize_kernel(
    const float* __restrict__ b, float* __restrict__ out)
{
    int warpId = (blockIdx.x * blockDim.x + threadIdx.x) >> 5;
    int lane = threadIdx.x & 31;
    if (warpId >= N_NODES) return;
    float4 v = g_agg2[(size_t)warpId * 32 + lane];
    float4 bb = ((const float4*)b)[lane];
    v.x += bb.x; v.y += bb.y; v.z += bb.z; v.w += bb.w;
    float s = v.x * v.x + v.y * v.y + v.z * v.z + v.w * v.w;
#pragma unroll
    for (int m = 16; m > 0; m >>= 1) s += __shfl_xor_sync(0xffffffffu, s, m);
    float nrm = sqrtf(s);
    float inv = 1.0f / fmaxf(nrm, 1e-12f);
    v.x *= inv; v.y *= inv; v.z *= inv; v.w *= inv;
    ((float4*)out)[(size_t)warpId * 32 + lane] = v;
}

// ---------------------------------------------------------------------------
// Launch
// ---------------------------------------------------------------------------
extern "C" void kernel_launch(void* const* d_in, const int* in_sizes, int n_in,
                              void* d_out, int out_size) {
    const float* x  = (const float*)d_in[0];
    const int*   ei = (const int*)d_in[1];      // int32 (JAX x64-disabled)
    const float* W1 = (const float*)d_in[2];
    const float* b1 = (const float*)d_in[3];
    const float* W2 = (const float*)d_in[4];
    const float* b2 = (const float*)d_in[5];
    float* out = (float*)d_out;

    const int E = in_sizes[1] / 2;
    const int* src = ei;
    const int* dst = ei + E;

    // 1) degrees -> dinv
    init_deg_kernel<<<(N_NODES + 255) / 256, 256>>>();
    deg_accum_kernel<<<(E + 255) / 256, 256>>>(dst, E);
    dinv_finalize_kernel<<<(N_NODES + 255) / 256, 256>>>();

    // 2) g_h1 = x @ W1  (tensor-core, bf16 split)
    {
        dim3 grid((N_NODES + 127) / 128, C_HID / 128);
        mma_gemm<<<grid, 256>>>(x, W1, N_NODES, C_IN, 0);
    }

    // 3) aggregation layer 1
    {
        int C4 = C_HID / 4;
        int total = N_NODES * C4;
        selfloop_init_kernel<<<(total + 255) / 256, 256>>>(C4, 0);
        int wpb = 256 / 32;
        scatter_edges_kernel<<<(E + wpb - 1) / wpb, 256>>>(src, dst, E, C4, 0);
    }

    // 4) g_h1 = relu(g_agg1 + b1)
    {
        int C4 = C_HID / 4;
        int total = N_NODES * C4;
        bias_relu_kernel<<<(total + 255) / 256, 256>>>(b1, C4);
    }

    // 5) g_h2 = g_h1 @ W2  (tensor-core, bf16 split)
    {
        dim3 grid((N_NODES + 127) / 128, C_OUT / 128);
        mma_gemm<<<grid, 256>>>(nullptr, W2, N_NODES, C_HID, 1);
    }

    // 6) aggregation layer 2
    {
        int C4 = C_OUT / 4;
        int total = N_NODES * C4;
        selfloop_init_kernel<<<(total + 255) / 256, 256>>>(C4, 1);
        int wpb = 256 / 32;
        scatter_edges_kernel<<<(E + wpb - 1) / wpb, 256>>>(src, dst, E, C4, 1);
    }

    // 7) out = normalize(g_agg2 + b2)
    {
        int wpb = 256 / 32;
        final_normalize_kernel<<<(N_NODES + wpb - 1) / wpb, 256>>>(b2, out);
    }
}

// round 5
// speedup vs baseline: 2.4133x; 1.2898x over previous
#include <cuda_runtime.h>
#include <cuda_bf16.h>
#include <stdint.h>

// Problem constants (from reference setup_inputs)
#define N_NODES 50000
#define C_IN    1536
#define C_HID   256
#define C_OUT   128

// ---------------------------------------------------------------------------
// Device-global scratch (no allocation allowed)
// ---------------------------------------------------------------------------
__device__ float4 g_h1  [N_NODES * C_HID / 4];  // GEMM1 out (f32, for scatter)
__device__ float4 g_agg1[N_NODES * C_HID / 4];
__device__ float4 g_h2  [N_NODES * C_OUT / 4];  // GEMM2 out
__device__ float4 g_agg2[N_NODES * C_OUT / 4];
__device__ float  g_dinv[N_NODES];

// bf16 hi/lo splits (precomputed once per launch)
__device__ __nv_bfloat16 g_xhi [N_NODES * C_IN];
__device__ __nv_bfloat16 g_xlo [N_NODES * C_IN];
__device__ __nv_bfloat16 g_zhi [N_NODES * C_HID];
__device__ __nv_bfloat16 g_zlo [N_NODES * C_HID];
__device__ __nv_bfloat16 g_w1hi[C_IN * C_HID];
__device__ __nv_bfloat16 g_w1lo[C_IN * C_HID];
__device__ __nv_bfloat16 g_w2hi[C_HID * C_OUT];
__device__ __nv_bfloat16 g_w2lo[C_HID * C_OUT];

// ---------------------------------------------------------------------------
// degree / dinv
// ---------------------------------------------------------------------------
__global__ void init_deg_kernel() {
    int i = blockIdx.x * blockDim.x + threadIdx.x;
    if (i < N_NODES) g_dinv[i] = 1.0f;
}

__global__ void deg_accum_kernel(const int* __restrict__ dst, int E) {
    int i = blockIdx.x * blockDim.x + threadIdx.x;
    if (i < E) {
        unsigned d = (unsigned)dst[i];
        if (d < N_NODES) atomicAdd(&g_dinv[d], 1.0f);
    }
}

__global__ void dinv_finalize_kernel() {
    int i = blockIdx.x * blockDim.x + threadIdx.x;
    if (i < N_NODES) g_dinv[i] = rsqrtf(g_dinv[i]);
}

// ---------------------------------------------------------------------------
// f32 -> (hi, lo) bf16 split.  which: 0=x, 1=W1, 2=W2
// ---------------------------------------------------------------------------
__global__ void split_kernel(const float* __restrict__ in, int n4, int which) {
    __nv_bfloat16* hi = (which == 0) ? g_xhi : (which == 1) ? g_w1hi : g_w2hi;
    __nv_bfloat16* lo = (which == 0) ? g_xlo : (which == 1) ? g_w1lo : g_w2lo;
    int i = blockIdx.x * blockDim.x + threadIdx.x;
    if (i >= n4) return;
    float4 v = ((const float4*)in)[i];
    float f[4] = {v.x, v.y, v.z, v.w};
    __nv_bfloat16 h[4], l[4];
#pragma unroll
    for (int j = 0; j < 4; ++j) {
        h[j] = __float2bfloat16_rn(f[j]);
        l[j] = __float2bfloat16_rn(f[j] - __bfloat162float(h[j]));
    }
    ((__nv_bfloat162*)hi)[2 * i]     = __nv_bfloat162(h[0], h[1]);
    ((__nv_bfloat162*)hi)[2 * i + 1] = __nv_bfloat162(h[2], h[3]);
    ((__nv_bfloat162*)lo)[2 * i]     = __nv_bfloat162(l[0], l[1]);
    ((__nv_bfloat162*)lo)[2 * i + 1] = __nv_bfloat162(l[2], l[3]);
}

// ---------------------------------------------------------------------------
// PTX helpers
// ---------------------------------------------------------------------------
__device__ __forceinline__ void mma_bf16(float c[4], const uint32_t a[4],
                                         const uint32_t b[2]) {
    asm volatile(
        "mma.sync.aligned.m16n8k16.row.col.f32.bf16.bf16.f32 "
        "{%0,%1,%2,%3}, {%4,%5,%6,%7}, {%8,%9}, {%0,%1,%2,%3};\n"
        : "+f"(c[0]), "+f"(c[1]), "+f"(c[2]), "+f"(c[3])
        : "r"(a[0]), "r"(a[1]), "r"(a[2]), "r"(a[3]), "r"(b[0]), "r"(b[1]));
}

__device__ __forceinline__ void ldsm_x4(uint32_t r[4], uint32_t addr) {
    asm volatile("ldmatrix.sync.aligned.m8n8.x4.shared.b16 {%0,%1,%2,%3}, [%4];"
                 : "=r"(r[0]), "=r"(r[1]), "=r"(r[2]), "=r"(r[3]) : "r"(addr));
}

__device__ __forceinline__ void ldsm_x4_t(uint32_t r[4], uint32_t addr) {
    asm volatile("ldmatrix.sync.aligned.m8n8.x4.trans.shared.b16 {%0,%1,%2,%3}, [%4];"
                 : "=r"(r[0]), "=r"(r[1]), "=r"(r[2]), "=r"(r[3]) : "r"(addr));
}

__device__ __forceinline__ void cp_async16(uint32_t saddr, const void* g, int srcbytes) {
    asm volatile("cp.async.cg.shared.global [%0], [%1], 16, %2;"
                 :: "r"(saddr), "l"(g), "r"(srcbytes));
}

// ---------------------------------------------------------------------------
// Split-bf16 tensor-core GEMM.  C[M,N] = A[M,K] @ B[K,N], fp32 out.
// 3-term: Ah*Bh + Ah*Bl + Al*Bh.  BM=64, BN=N (template), BK=32.
// cp.async double-buffered staging, ldmatrix fragments.
// MODE 0: A = x-split  (K=1536, N=256), C = g_h1
// MODE 1: A = z-split  (K=256,  N=128), C = g_h2
// ---------------------------------------------------------------------------
template <int MODE>
__global__ __launch_bounds__(256, 2) void mma_gemm_sp(int M) {
    constexpr int BN   = MODE ? C_OUT : C_HID;     // 128 / 256
    constexpr int K    = MODE ? C_HID : C_IN;      // 256 / 1536
    constexpr int BM   = 64, BK = 32;
    constexpr int AST  = 80;                       // A smem row stride (bytes)
    constexpr int BROW = BN * 2 + 16;              // B smem row stride (bytes)
    constexpr int A_STAGE = 2 * BM * AST;          // hi+lo
    constexpr int B_STAGE = 2 * BK * BROW;
    constexpr int NT = BN / 32;                    // n8-tiles per warp (8 / 4)
    constexpr int KT = K / BK;

    const __nv_bfloat16* Ah = MODE ? g_zhi : g_xhi;
    const __nv_bfloat16* Al = MODE ? g_zlo : g_xlo;
    const __nv_bfloat16* Bh = MODE ? g_w2hi : g_w1hi;
    const __nv_bfloat16* Bl = MODE ? g_w2lo : g_w1lo;
    float*               C  = MODE ? (float*)g_h2 : (float*)g_h1;

    extern __shared__ char smem[];
    uint32_t sA = (uint32_t)__cvta_generic_to_shared(smem);
    uint32_t sB = sA + 2 * A_STAGE;

    const int tid = threadIdx.x, lane = tid & 31, warp = tid >> 5;
    const int warpM = warp & 1, warpN = warp >> 1;
    const int g = lane >> 2, t4 = lane & 3;
    const int rowBase = blockIdx.x * BM;

    float acc[2][NT][4] = {};

    auto stage = [&](int kt, int s) {
        const int k0 = kt * BK;
        // A: 512 chunks of 16B (hi 256 + lo 256)
#pragma unroll
        for (int it = 0; it < 2; ++it) {
            int c = tid + it * 256;
            int hl = c >> 8, cc = c & 255;
            int row = cc >> 2, kc = cc & 3;
            int grow = rowBase + row;
            int sz = (grow < M) ? 16 : 0;
            if (grow >= M) grow = M - 1;
            const __nv_bfloat16* src = (hl ? Al : Ah) + (size_t)grow * K + k0 + kc * 8;
            cp_async16(sA + s * A_STAGE + hl * (BM * AST) + row * AST + kc * 16, src, sz);
        }
        // B: 2*BK*(BN/8) chunks of 16B
        constexpr int BCH = 2 * BK * (BN / 8);
#pragma unroll
        for (int it = 0; it < BCH / 256; ++it) {
            int c = tid + it * 256;
            int hl = c / (BCH / 2);
            int cc = c % (BCH / 2);
            int row = cc / (BN / 8), nc = cc % (BN / 8);
            const __nv_bfloat16* src = (hl ? Bl : Bh) + (size_t)(k0 + row) * BN + nc * 8;
            cp_async16(sB + s * B_STAGE + hl * (BK * BROW) + row * BROW + nc * 16, src, 16);
        }
        asm volatile("cp.async.commit_group;");
    };

    stage(0, 0);
    for (int kt = 0; kt < KT; ++kt) {
        const int s = kt & 1;
        if (kt + 1 < KT) {
            stage(kt + 1, s ^ 1);
            asm volatile("cp.async.wait_group 1;");
        } else {
            asm volatile("cp.async.wait_group 0;");
        }
        __syncthreads();

        const int q = lane >> 3;
#pragma unroll
        for (int ks = 0; ks < 2; ++ks) {
            uint32_t a[2][2][4];     // [mi][hl][4]
#pragma unroll
            for (int mi = 0; mi < 2; ++mi) {
                int row  = warpM * 32 + mi * 16 + (q & 1) * 8 + (lane & 7);
                int colb = (ks * 16 + (q >> 1) * 8) * 2;
#pragma unroll
                for (int hl = 0; hl < 2; ++hl)
                    ldsm_x4(a[mi][hl], sA + s * A_STAGE + hl * (BM * AST) + row * AST + colb);
            }
#pragma unroll
            for (int np = 0; np < NT / 2; ++np) {
                uint32_t bq[2][4];
                int krow = ks * 16 + (q & 1) * 8 + (lane & 7);
                int ncol = warpN * (BN / 4) + np * 16 + (q >> 1) * 8;
#pragma unroll
                for (int hl = 0; hl < 2; ++hl)
                    ldsm_x4_t(bq[hl], sB + s * B_STAGE + hl * (BK * BROW) + krow * BROW + ncol * 2);
#pragma unroll
                for (int half = 0; half < 2; ++half) {
                    uint32_t bh[2] = {bq[0][half * 2], bq[0][half * 2 + 1]};
                    uint32_t bl[2] = {bq[1][half * 2], bq[1][half * 2 + 1]};
                    const int nt = np * 2 + half;
#pragma unroll
                    for (int mi = 0; mi < 2; ++mi) {
                        mma_bf16(acc[mi][nt], a[mi][0], bh);
                        mma_bf16(acc[mi][nt], a[mi][0], bl);
                        mma_bf16(acc[mi][nt], a[mi][1], bh);
                    }
                }
            }
        }
        __syncthreads();
    }

    // epilogue
#pragma unroll
    for (int mi = 0; mi < 2; ++mi)
#pragma unroll
        for (int nt = 0; nt < NT; ++nt) {
            int col = warpN * (BN / 4) + nt * 8 + t4 * 2;
            int r0  = rowBase + warpM * 32 + mi * 16 + g;
            if (r0 < M)
                *(float2*)(C + (size_t)r0 * BN + col) = make_float2(acc[mi][nt][0], acc[mi][nt][1]);
            int r1 = r0 + 8;
            if (r1 < M)
                *(float2*)(C + (size_t)r1 * BN + col) = make_float2(acc[mi][nt][2], acc[mi][nt][3]);
        }
}

// ---------------------------------------------------------------------------
// Self-loop init: agg[i][c] = h[i][c] * dinv[i]^2
// ---------------------------------------------------------------------------
__global__ void selfloop_init_kernel(int C4, int layer) {
    const float4* h   = (layer == 0) ? g_h1   : g_h2;
    float4*       agg = (layer == 0) ? g_agg1 : g_agg2;
    int idx = blockIdx.x * blockDim.x + threadIdx.x;
    int total = N_NODES * C4;
    if (idx >= total) return;
    int row = idx / C4;
    float w = g_dinv[row];
    w = w * w;
    float4 v = h[idx];
    v.x *= w; v.y *= w; v.z *= w; v.w *= w;
    agg[idx] = v;
}

// ---------------------------------------------------------------------------
// Edge scatter: one warp per edge, red.global.add.v4.f32
// ---------------------------------------------------------------------------
__device__ __forceinline__ void red_add_v4(float* p, float4 v) {
    asm volatile("red.global.add.v4.f32 [%0], {%1, %2, %3, %4};"
                 :: "l"(p), "f"(v.x), "f"(v.y), "f"(v.z), "f"(v.w)
                 : "memory");
}

__global__ __launch_bounds__(256) void scatter_edges_kernel(
    const int* __restrict__ src, const int* __restrict__ dst,
    int E, int C4, int layer)
{
    const float4* h   = (layer == 0) ? g_h1 : g_h2;
    float*        agg = (layer == 0) ? (float*)g_agg1 : (float*)g_agg2;

    int warpId = (blockIdx.x * blockDim.x + threadIdx.x) >> 5;
    int lane = threadIdx.x & 31;
    if (warpId >= E) return;
    unsigned s = (unsigned)src[warpId];
    unsigned d = (unsigned)dst[warpId];
    if (s >= N_NODES || d >= N_NODES) return;
    float w = g_dinv[s] * g_dinv[d];
    const float4* hp = h + (size_t)s * C4;
    float*        ap = agg + (size_t)d * C4 * 4;
#pragma unroll 2
    for (int j = lane; j < C4; j += 32) {
        float4 v = __ldg(hp + j);
        v.x *= w; v.y *= w; v.z *= w; v.w *= w;
        red_add_v4(ap + j * 4, v);
    }
}

// ---------------------------------------------------------------------------
// z = relu(agg1 + b1) -> split into g_zhi / g_zlo (bf16)
// ---------------------------------------------------------------------------
__global__ void bias_relu_split_kernel(const float* __restrict__ b) {
    constexpr int C4 = C_HID / 4;
    int idx = blockIdx.x * blockDim.x + threadIdx.x;
    int total = N_NODES * C4;
    if (idx >= total) return;
    int c4 = idx % C4;
    float4 v = g_agg1[idx];
    float4 bb = ((const float4*)b)[c4];
    float f[4] = {fmaxf(v.x + bb.x, 0.f), fmaxf(v.y + bb.y, 0.f),
                  fmaxf(v.z + bb.z, 0.f), fmaxf(v.w + bb.w, 0.f)};
    __nv_bfloat16 h[4], l[4];
#pragma unroll
    for (int j = 0; j < 4; ++j) {
        h[j] = __float2bfloat16_rn(f[j]);
        l[j] = __float2bfloat16_rn(f[j] - __bfloat162float(h[j]));
    }
    ((__nv_bfloat162*)g_zhi)[2 * idx]     = __nv_bfloat162(h[0], h[1]);
    ((__nv_bfloat162*)g_zhi)[2 * idx + 1] = __nv_bfloat162(h[2], h[3]);
    ((__nv_bfloat162*)g_zlo)[2 * idx]     = __nv_bfloat162(l[0], l[1]);
    ((__nv_bfloat162*)g_zlo)[2 * idx + 1] = __nv_bfloat162(l[2], l[3]);
}

// ---------------------------------------------------------------------------
// out = normalize(g_agg2 + b2)
// ---------------------------------------------------------------------------
__global__ __launch_bounds__(256) void final_normalize_kernel(
    const float* __restrict__ b, float* __restrict__ out)
{
    int warpId = (blockIdx.x * blockDim.x + threadIdx.x) >> 5;
    int lane = threadIdx.x & 31;
    if (warpId >= N_NODES) return;
    float4 v = g_agg2[(size_t)warpId * 32 + lane];
    float4 bb = ((const float4*)b)[lane];
    v.x += bb.x; v.y += bb.y; v.z += bb.z; v.w += bb.w;
    float s = v.x * v.x + v.y * v.y + v.z * v.z + v.w * v.w;
#pragma unroll
    for (int m = 16; m > 0; m >>= 1) s += __shfl_xor_sync(0xffffffffu, s, m);
    float nrm = sqrtf(s);
    float inv = 1.0f / fmaxf(nrm, 1e-12f);
    v.x *= inv; v.y *= inv; v.z *= inv; v.w *= inv;
    ((float4*)out)[(size_t)warpId * 32 + lane] = v;
}

// ---------------------------------------------------------------------------
// Launch
// ---------------------------------------------------------------------------
extern "C" void kernel_launch(void* const* d_in, const int* in_sizes, int n_in,
                              void* d_out, int out_size) {
    const float* x  = (const float*)d_in[0];
    const int*   ei = (const int*)d_in[1];      // int32
    const float* W1 = (const float*)d_in[2];
    const float* b1 = (const float*)d_in[3];
    const float* W2 = (const float*)d_in[4];
    const float* b2 = (const float*)d_in[5];
    float* out = (float*)d_out;

    const int E = in_sizes[1] / 2;
    const int* src = ei;
    const int* dst = ei + E;

    // dynamic smem opt-in for the GEMMs (sizes > 48KB static limit)
    constexpr int SMEM0 = 2 * (2 * 64 * 80) + 2 * (2 * 32 * (256 * 2 + 16));  // 88064
    constexpr int SMEM1 = 2 * (2 * 64 * 80) + 2 * (2 * 32 * (128 * 2 + 16));  // 55296
    static bool attr_done = false;
    if (!attr_done) {
        cudaFuncSetAttribute(mma_gemm_sp<0>, cudaFuncAttributeMaxDynamicSharedMemorySize, SMEM0);
        cudaFuncSetAttribute(mma_gemm_sp<1>, cudaFuncAttributeMaxDynamicSharedMemorySize, SMEM1);
        attr_done = true;
    }

    // 0) precompute bf16 splits
    split_kernel<<<(N_NODES * C_IN / 4 + 255) / 256, 256>>>(x,  N_NODES * C_IN / 4, 0);
    split_kernel<<<(C_IN * C_HID / 4 + 255) / 256, 256>>>(W1, C_IN * C_HID / 4, 1);
    split_kernel<<<(C_HID * C_OUT / 4 + 255) / 256, 256>>>(W2, C_HID * C_OUT / 4, 2);

    // 1) degrees -> dinv
    init_deg_kernel<<<(N_NODES + 255) / 256, 256>>>();
    deg_accum_kernel<<<(E + 255) / 256, 256>>>(dst, E);
    dinv_finalize_kernel<<<(N_NODES + 255) / 256, 256>>>();

    // 2) g_h1 = x @ W1
    mma_gemm_sp<0><<<(N_NODES + 63) / 64, 256, SMEM0>>>(N_NODES);

    // 3) aggregation layer 1
    {
        int C4 = C_HID / 4;
        selfloop_init_kernel<<<(N_NODES * C4 + 255) / 256, 256>>>(C4, 0);
        scatter_edges_kernel<<<(E + 7) / 8, 256>>>(src, dst, E, C4, 0);
    }

    // 4) z = relu(agg1 + b1) -> bf16 split
    bias_relu_split_kernel<<<(N_NODES * (C_HID / 4) + 255) / 256, 256>>>(b1);

    // 5) g_h2 = z @ W2
    mma_gemm_sp<1><<<(N_NODES + 63) / 64, 256, SMEM1>>>(N_NODES);

    // 6) aggregation layer 2
    {
        int C4 = C_OUT / 4;
        selfloop_init_kernel<<<(N_NODES * C4 + 255) / 256, 256>>>(C4, 1);
        scatter_edges_kernel<<<(E + 7) / 8, 256>>>(src, dst, E, C4, 1);
    }

    // 7) out = normalize(g_agg2 + b2)
    final_normalize_kernel<<<(N_NODES + 7) / 8, 256>>>(b2, out);
}

// round 6
// speedup vs baseline: 3.3867x; 1.4033x over previous
#include <cuda_runtime.h>
#include <cuda_bf16.h>
#include <stdint.h>

// Problem constants (from reference setup_inputs)
#define N_NODES 50000
#define C_IN    1536
#define C_HID   256
#define C_OUT   128
#define E_MAX   1600000

// ---------------------------------------------------------------------------
// Device-global scratch (no allocation allowed)
// ---------------------------------------------------------------------------
__device__ float4 g_h1 [N_NODES * C_HID / 4];   // GEMM1 out (f32)
__device__ float4 g_h2 [N_NODES * C_OUT / 4];   // GEMM2 out (f32)
__device__ float  g_dinv[N_NODES];

// CSR-by-dst edge structure (built per launch)
__device__ int    g_deg   [N_NODES];
__device__ int    g_eoff  [N_NODES + 1];
__device__ int    g_cursor[N_NODES];
__device__ int    g_esrc  [E_MAX];
__device__ float  g_ew    [E_MAX];

// bf16 hi/lo splits
__device__ __nv_bfloat16 g_xhi [N_NODES * C_IN];
__device__ __nv_bfloat16 g_xlo [N_NODES * C_IN];
__device__ __nv_bfloat16 g_zhi [N_NODES * C_HID];
__device__ __nv_bfloat16 g_zlo [N_NODES * C_HID];
__device__ __nv_bfloat16 g_w1hi[C_IN * C_HID];
__device__ __nv_bfloat16 g_w1lo[C_IN * C_HID];
__device__ __nv_bfloat16 g_w2hi[C_HID * C_OUT];
__device__ __nv_bfloat16 g_w2lo[C_HID * C_OUT];

// ---------------------------------------------------------------------------
// degree histogram / dinv
// ---------------------------------------------------------------------------
__global__ void zero_deg_kernel() {
    int i = blockIdx.x * blockDim.x + threadIdx.x;
    if (i < N_NODES) g_deg[i] = 0;
}

__global__ void deg_accum_kernel(const int* __restrict__ dst, int E) {
    int i = blockIdx.x * blockDim.x + threadIdx.x;
    if (i < E) {
        unsigned d = (unsigned)dst[i];
        if (d < N_NODES) atomicAdd(&g_deg[d], 1);
    }
}

__global__ void dinv_finalize_kernel() {
    int i = blockIdx.x * blockDim.x + threadIdx.x;
    if (i < N_NODES) g_dinv[i] = rsqrtf((float)(g_deg[i] + 1));  // +1 self-loop
}

// ---------------------------------------------------------------------------
// Single-block exclusive scan of g_deg -> g_eoff / g_cursor
// ---------------------------------------------------------------------------
#define SCAN_T 1024
__global__ __launch_bounds__(SCAN_T) void scan_kernel() {
    __shared__ int sh[SCAN_T];
    const int tid = threadIdx.x;
    const int PER = (N_NODES + SCAN_T - 1) / SCAN_T;  // 49
    const int base = tid * PER;
    int s = 0;
    for (int j = 0; j < PER; ++j) {
        int i = base + j;
        if (i < N_NODES) s += g_deg[i];
    }
    sh[tid] = s;
    __syncthreads();
    for (int off = 1; off < SCAN_T; off <<= 1) {
        int v = (tid >= off) ? sh[tid - off] : 0;
        __syncthreads();
        sh[tid] += v;
        __syncthreads();
    }
    int running = sh[tid] - s;   // exclusive prefix for this chunk
    for (int j = 0; j < PER; ++j) {
        int i = base + j;
        if (i < N_NODES) {
            g_eoff[i]   = running;
            g_cursor[i] = running;
            running += g_deg[i];
        }
    }
    if (tid == SCAN_T - 1) g_eoff[N_NODES] = sh[SCAN_T - 1];
}

// ---------------------------------------------------------------------------
// Bucket edges by dst; precompute norm weight
// ---------------------------------------------------------------------------
__global__ void bucket_kernel(const int* __restrict__ src,
                              const int* __restrict__ dst, int E) {
    int e = blockIdx.x * blockDim.x + threadIdx.x;
    if (e >= E) return;
    unsigned s = (unsigned)src[e];
    unsigned d = (unsigned)dst[e];
    if (s >= N_NODES || d >= N_NODES) return;
    int pos = atomicAdd(&g_cursor[d], 1);
    if (pos < E_MAX) {
        g_esrc[pos] = (int)s;
        g_ew[pos]   = g_dinv[s] * g_dinv[d];
    }
}

// ---------------------------------------------------------------------------
// f32 -> (hi, lo) bf16 split.  which: 0=x, 1=W1, 2=W2
// ---------------------------------------------------------------------------
__global__ void split_kernel(const float* __restrict__ in, int n4, int which) {
    __nv_bfloat16* hi = (which == 0) ? g_xhi : (which == 1) ? g_w1hi : g_w2hi;
    __nv_bfloat16* lo = (which == 0) ? g_xlo : (which == 1) ? g_w1lo : g_w2lo;
    int i = blockIdx.x * blockDim.x + threadIdx.x;
    if (i >= n4) return;
    float4 v = ((const float4*)in)[i];
    float f[4] = {v.x, v.y, v.z, v.w};
    __nv_bfloat16 h[4], l[4];
#pragma unroll
    for (int j = 0; j < 4; ++j) {
        h[j] = __float2bfloat16_rn(f[j]);
        l[j] = __float2bfloat16_rn(f[j] - __bfloat162float(h[j]));
    }
    ((__nv_bfloat162*)hi)[2 * i]     = __nv_bfloat162(h[0], h[1]);
    ((__nv_bfloat162*)hi)[2 * i + 1] = __nv_bfloat162(h[2], h[3]);
    ((__nv_bfloat162*)lo)[2 * i]     = __nv_bfloat162(l[0], l[1]);
    ((__nv_bfloat162*)lo)[2 * i + 1] = __nv_bfloat162(l[2], l[3]);
}

// ---------------------------------------------------------------------------
// PTX helpers
// ---------------------------------------------------------------------------
__device__ __forceinline__ void mma_bf16(float c[4], const uint32_t a[4],
                                         const uint32_t b[2]) {
    asm volatile(
        "mma.sync.aligned.m16n8k16.row.col.f32.bf16.bf16.f32 "
        "{%0,%1,%2,%3}, {%4,%5,%6,%7}, {%8,%9}, {%0,%1,%2,%3};\n"
        : "+f"(c[0]), "+f"(c[1]), "+f"(c[2]), "+f"(c[3])
        : "r"(a[0]), "r"(a[1]), "r"(a[2]), "r"(a[3]), "r"(b[0]), "r"(b[1]));
}

__device__ __forceinline__ void ldsm_x4(uint32_t r[4], uint32_t addr) {
    asm volatile("ldmatrix.sync.aligned.m8n8.x4.shared.b16 {%0,%1,%2,%3}, [%4];"
                 : "=r"(r[0]), "=r"(r[1]), "=r"(r[2]), "=r"(r[3]) : "r"(addr));
}

__device__ __forceinline__ void ldsm_x4_t(uint32_t r[4], uint32_t addr) {
    asm volatile("ldmatrix.sync.aligned.m8n8.x4.trans.shared.b16 {%0,%1,%2,%3}, [%4];"
                 : "=r"(r[0]), "=r"(r[1]), "=r"(r[2]), "=r"(r[3]) : "r"(addr));
}

__device__ __forceinline__ void cp_async16(uint32_t saddr, const void* g, int srcbytes) {
    asm volatile("cp.async.cg.shared.global [%0], [%1], 16, %2;"
                 :: "r"(saddr), "l"(g), "r"(srcbytes));
}

// ---------------------------------------------------------------------------
// Split-bf16 tensor-core GEMM (unchanged from round 5).
// MODE 0: A = x-split  (K=1536, N=256), C = g_h1
// MODE 1: A = z-split  (K=256,  N=128), C = g_h2
// ---------------------------------------------------------------------------
template <int MODE>
__global__ __launch_bounds__(256, 2) void mma_gemm_sp(int M) {
    constexpr int BN   = MODE ? C_OUT : C_HID;
    constexpr int K    = MODE ? C_HID : C_IN;
    constexpr int BM   = 64, BK = 32;
    constexpr int AST  = 80;
    constexpr int BROW = BN * 2 + 16;
    constexpr int A_STAGE = 2 * BM * AST;
    constexpr int B_STAGE = 2 * BK * BROW;
    constexpr int NT = BN / 32;
    constexpr int KT = K / BK;

    const __nv_bfloat16* Ah = MODE ? g_zhi : g_xhi;
    const __nv_bfloat16* Al = MODE ? g_zlo : g_xlo;
    const __nv_bfloat16* Bh = MODE ? g_w2hi : g_w1hi;
    const __nv_bfloat16* Bl = MODE ? g_w2lo : g_w1lo;
    float*               C  = MODE ? (float*)g_h2 : (float*)g_h1;

    extern __shared__ char smem[];
    uint32_t sA = (uint32_t)__cvta_generic_to_shared(smem);
    uint32_t sB = sA + 2 * A_STAGE;

    const int tid = threadIdx.x, lane = tid & 31, warp = tid >> 5;
    const int warpM = warp & 1, warpN = warp >> 1;
    const int g = lane >> 2, t4 = lane & 3;
    const int rowBase = blockIdx.x * BM;

    float acc[2][NT][4] = {};

    auto stage = [&](int kt, int s) {
        const int k0 = kt * BK;
#pragma unroll
        for (int it = 0; it < 2; ++it) {
            int c = tid + it * 256;
            int hl = c >> 8, cc = c & 255;
            int row = cc >> 2, kc = cc & 3;
            int grow = rowBase + row;
            int sz = (grow < M) ? 16 : 0;
            if (grow >= M) grow = M - 1;
            const __nv_bfloat16* src = (hl ? Al : Ah) + (size_t)grow * K + k0 + kc * 8;
            cp_async16(sA + s * A_STAGE + hl * (BM * AST) + row * AST + kc * 16, src, sz);
        }
        constexpr int BCH = 2 * BK * (BN / 8);
#pragma unroll
        for (int it = 0; it < BCH / 256; ++it) {
            int c = tid + it * 256;
            int hl = c / (BCH / 2);
            int cc = c % (BCH / 2);
            int row = cc / (BN / 8), nc = cc % (BN / 8);
            const __nv_bfloat16* src = (hl ? Bl : Bh) + (size_t)(k0 + row) * BN + nc * 8;
            cp_async16(sB + s * B_STAGE + hl * (BK * BROW) + row * BROW + nc * 16, src, 16);
        }
        asm volatile("cp.async.commit_group;");
    };

    stage(0, 0);
    for (int kt = 0; kt < KT; ++kt) {
        const int s = kt & 1;
        if (kt + 1 < KT) {
            stage(kt + 1, s ^ 1);
            asm volatile("cp.async.wait_group 1;");
        } else {
            asm volatile("cp.async.wait_group 0;");
        }
        __syncthreads();

        const int q = lane >> 3;
#pragma unroll
        for (int ks = 0; ks < 2; ++ks) {
            uint32_t a[2][2][4];
#pragma unroll
            for (int mi = 0; mi < 2; ++mi) {
                int row  = warpM * 32 + mi * 16 + (q & 1) * 8 + (lane & 7);
                int colb = (ks * 16 + (q >> 1) * 8) * 2;
#pragma unroll
                for (int hl = 0; hl < 2; ++hl)
                    ldsm_x4(a[mi][hl], sA + s * A_STAGE + hl * (BM * AST) + row * AST + colb);
            }
#pragma unroll
            for (int np = 0; np < NT / 2; ++np) {
                uint32_t bq[2][4];
                int krow = ks * 16 + (q & 1) * 8 + (lane & 7);
                int ncol = warpN * (BN / 4) + np * 16 + (q >> 1) * 8;
#pragma unroll
                for (int hl = 0; hl < 2; ++hl)
                    ldsm_x4_t(bq[hl], sB + s * B_STAGE + hl * (BK * BROW) + krow * BROW + ncol * 2);
#pragma unroll
                for (int half = 0; half < 2; ++half) {
                    uint32_t bh[2] = {bq[0][half * 2], bq[0][half * 2 + 1]};
                    uint32_t bl[2] = {bq[1][half * 2], bq[1][half * 2 + 1]};
                    const int nt = np * 2 + half;
#pragma unroll
                    for (int mi = 0; mi < 2; ++mi) {
                        mma_bf16(acc[mi][nt], a[mi][0], bh);
                        mma_bf16(acc[mi][nt], a[mi][0], bl);
                        mma_bf16(acc[mi][nt], a[mi][1], bh);
                    }
                }
            }
        }
        __syncthreads();
    }

#pragma unroll
    for (int mi = 0; mi < 2; ++mi)
#pragma unroll
        for (int nt = 0; nt < NT; ++nt) {
            int col = warpN * (BN / 4) + nt * 8 + t4 * 2;
            int r0  = rowBase + warpM * 32 + mi * 16 + g;
            if (r0 < M)
                *(float2*)(C + (size_t)r0 * BN + col) = make_float2(acc[mi][nt][0], acc[mi][nt][1]);
            int r1 = r0 + 8;
            if (r1 < M)
                *(float2*)(C + (size_t)r1 * BN + col) = make_float2(acc[mi][nt][2], acc[mi][nt][3]);
        }
}

// ---------------------------------------------------------------------------
// Layer-1 gather aggregation (warp per node, C=256):
//   acc = h1[i]*dinv^2 + sum_e h1[src]*w;  z = relu(acc + b1) -> zhi/zlo
// ---------------------------------------------------------------------------
__global__ __launch_bounds__(256) void gather_agg1_kernel(const float* __restrict__ b1) {
    int node = (blockIdx.x * blockDim.x + threadIdx.x) >> 5;
    int lane = threadIdx.x & 31;
    if (node >= N_NODES) return;

    const float4* h = g_h1;
    float di = g_dinv[node];
    float ws = di * di;
    size_t rb = (size_t)node * 64;
    float4 a0 = h[rb + lane];
    float4 a1 = h[rb + 32 + lane];
    a0.x *= ws; a0.y *= ws; a0.z *= ws; a0.w *= ws;
    a1.x *= ws; a1.y *= ws; a1.z *= ws; a1.w *= ws;

    int beg = g_eoff[node], end = g_eoff[node + 1];
    int k = beg;
    for (; k + 2 <= end; k += 2) {
        int s0 = g_esrc[k], s1 = g_esrc[k + 1];
        float w0 = g_ew[k], w1 = g_ew[k + 1];
        size_t r0 = (size_t)s0 * 64, r1 = (size_t)s1 * 64;
        float4 v00 = h[r0 + lane],      v01 = h[r0 + 32 + lane];
        float4 v10 = h[r1 + lane],      v11 = h[r1 + 32 + lane];
        a0.x += v00.x * w0; a0.y += v00.y * w0; a0.z += v00.z * w0; a0.w += v00.w * w0;
        a1.x += v01.x * w0; a1.y += v01.y * w0; a1.z += v01.z * w0; a1.w += v01.w * w0;
        a0.x += v10.x * w1; a0.y += v10.y * w1; a0.z += v10.z * w1; a0.w += v10.w * w1;
        a1.x += v11.x * w1; a1.y += v11.y * w1; a1.z += v11.z * w1; a1.w += v11.w * w1;
    }
    if (k < end) {
        int s0 = g_esrc[k]; float w0 = g_ew[k];
        size_t r0 = (size_t)s0 * 64;
        float4 v00 = h[r0 + lane], v01 = h[r0 + 32 + lane];
        a0.x += v00.x * w0; a0.y += v00.y * w0; a0.z += v00.z * w0; a0.w += v00.w * w0;
        a1.x += v01.x * w0; a1.y += v01.y * w0; a1.z += v01.z * w0; a1.w += v01.w * w0;
    }

    float4 bb0 = ((const float4*)b1)[lane];
    float4 bb1 = ((const float4*)b1)[lane + 32];
    float f0[4] = {fmaxf(a0.x + bb0.x, 0.f), fmaxf(a0.y + bb0.y, 0.f),
                   fmaxf(a0.z + bb0.z, 0.f), fmaxf(a0.w + bb0.w, 0.f)};
    float f1[4] = {fmaxf(a1.x + bb1.x, 0.f), fmaxf(a1.y + bb1.y, 0.f),
                   fmaxf(a1.z + bb1.z, 0.f), fmaxf(a1.w + bb1.w, 0.f)};

    __nv_bfloat162* zh = (__nv_bfloat162*)(g_zhi + (size_t)node * C_HID);
    __nv_bfloat162* zl = (__nv_bfloat162*)(g_zlo + (size_t)node * C_HID);
#pragma unroll
    for (int half = 0; half < 2; ++half) {
        float* f = half ? f1 : f0;
        int idx = 2 * (lane + half * 32);
        __nv_bfloat16 h0 = __float2bfloat16_rn(f[0]);
        __nv_bfloat16 h1v = __float2bfloat16_rn(f[1]);
        __nv_bfloat16 h2v = __float2bfloat16_rn(f[2]);
        __nv_bfloat16 h3 = __float2bfloat16_rn(f[3]);
        zh[idx]     = __nv_bfloat162(h0, h1v);
        zh[idx + 1] = __nv_bfloat162(h2v, h3);
        zl[idx]     = __nv_bfloat162(__float2bfloat16_rn(f[0] - __bfloat162float(h0)),
                                     __float2bfloat16_rn(f[1] - __bfloat162float(h1v)));
        zl[idx + 1] = __nv_bfloat162(__float2bfloat16_rn(f[2] - __bfloat162float(h2v)),
                                     __float2bfloat16_rn(f[3] - __bfloat162float(h3)));
    }
}

// ---------------------------------------------------------------------------
// Layer-2 gather aggregation + bias + row-normalize (warp per node, C=128)
// ---------------------------------------------------------------------------
__global__ __launch_bounds__(256) void gather_agg2_kernel(const float* __restrict__ b2,
                                                          float* __restrict__ out) {
    int node = (blockIdx.x * blockDim.x + threadIdx.x) >> 5;
    int lane = threadIdx.x & 31;
    if (node >= N_NODES) return;

    const float4* h = g_h2;
    float di = g_dinv[node];
    float ws = di * di;
    float4 a = h[(size_t)node * 32 + lane];
    a.x *= ws; a.y *= ws; a.z *= ws; a.w *= ws;

    int beg = g_eoff[node], end = g_eoff[node + 1];
    int k = beg;
    for (; k + 2 <= end; k += 2) {
        int s0 = g_esrc[k], s1 = g_esrc[k + 1];
        float w0 = g_ew[k], w1 = g_ew[k + 1];
        float4 v0 = h[(size_t)s0 * 32 + lane];
        float4 v1 = h[(size_t)s1 * 32 + lane];
        a.x += v0.x * w0; a.y += v0.y * w0; a.z += v0.z * w0; a.w += v0.w * w0;
        a.x += v1.x * w1; a.y += v1.y * w1; a.z += v1.z * w1; a.w += v1.w * w1;
    }
    if (k < end) {
        int s0 = g_esrc[k]; float w0 = g_ew[k];
        float4 v0 = h[(size_t)s0 * 32 + lane];
        a.x += v0.x * w0; a.y += v0.y * w0; a.z += v0.z * w0; a.w += v0.w * w0;
    }

    float4 bb = ((const float4*)b2)[lane];
    a.x += bb.x; a.y += bb.y; a.z += bb.z; a.w += bb.w;
    float s = a.x * a.x + a.y * a.y + a.z * a.z + a.w * a.w;
#pragma unroll
    for (int m = 16; m > 0; m >>= 1) s += __shfl_xor_sync(0xffffffffu, s, m);
    float inv = 1.0f / fmaxf(sqrtf(s), 1e-12f);
    a.x *= inv; a.y *= inv; a.z *= inv; a.w *= inv;
    ((float4*)out)[(size_t)node * 32 + lane] = a;
}

// ---------------------------------------------------------------------------
// Launch
// ---------------------------------------------------------------------------
extern "C" void kernel_launch(void* const* d_in, const int* in_sizes, int n_in,
                              void* d_out, int out_size) {
    const float* x  = (const float*)d_in[0];
    const int*   ei = (const int*)d_in[1];      // int32
    const float* W1 = (const float*)d_in[2];
    const float* b1 = (const float*)d_in[3];
    const float* W2 = (const float*)d_in[4];
    const float* b2 = (const float*)d_in[5];
    float* out = (float*)d_out;

    const int E = in_sizes[1] / 2;
    const int* src = ei;
    const int* dst = ei + E;

    constexpr int SMEM0 = 2 * (2 * 64 * 80) + 2 * (2 * 32 * (256 * 2 + 16));  // 88064
    constexpr int SMEM1 = 2 * (2 * 64 * 80) + 2 * (2 * 32 * (128 * 2 + 16));  // 55296
    static bool attr_done = false;
    if (!attr_done) {
        cudaFuncSetAttribute(mma_gemm_sp<0>, cudaFuncAttributeMaxDynamicSharedMemorySize, SMEM0);
        cudaFuncSetAttribute(mma_gemm_sp<1>, cudaFuncAttributeMaxDynamicSharedMemorySize, SMEM1);
        attr_done = true;
    }

    // 0) bf16 splits for GEMM operands
    split_kernel<<<(N_NODES * C_IN / 4 + 255) / 256, 256>>>(x,  N_NODES * C_IN / 4, 0);
    split_kernel<<<(C_IN * C_HID / 4 + 255) / 256, 256>>>(W1, C_IN * C_HID / 4, 1);
    split_kernel<<<(C_HID * C_OUT / 4 + 255) / 256, 256>>>(W2, C_HID * C_OUT / 4, 2);

    // 1) degree histogram -> dinv, CSR offsets, bucketed edges
    zero_deg_kernel<<<(N_NODES + 255) / 256, 256>>>();
    deg_accum_kernel<<<(E + 255) / 256, 256>>>(dst, E);
    dinv_finalize_kernel<<<(N_NODES + 255) / 256, 256>>>();
    scan_kernel<<<1, SCAN_T>>>();
    bucket_kernel<<<(E + 255) / 256, 256>>>(src, dst, E);

    // 2) g_h1 = x @ W1
    mma_gemm_sp<0><<<(N_NODES + 63) / 64, 256, SMEM0>>>(N_NODES);

    // 3) layer-1 aggregation + bias + relu + bf16 split (fused)
    gather_agg1_kernel<<<(N_NODES * 32 + 255) / 256, 256>>>(b1);

    // 4) g_h2 = z @ W2
    mma_gemm_sp<1><<<(N_NODES + 63) / 64, 256, SMEM1>>>(N_NODES);

    // 5) layer-2 aggregation + bias + normalize -> out (fused)
    gather_agg2_kernel<<<(N_NODES * 32 + 255) / 256, 256>>>(b2, out);
}

// round 7
// speedup vs baseline: 3.7091x; 1.0952x over previous
#include <cuda_runtime.h>
#include <cuda_bf16.h>
#include <stdint.h>

// Problem constants (from reference setup_inputs)
#define N_NODES 50000
#define C_IN    1536
#define C_HID   256
#define C_OUT   128
#define E_MAX   1600000

// ---------------------------------------------------------------------------
// Device-global scratch (no allocation allowed)
// ---------------------------------------------------------------------------
__device__ float4 g_h1 [N_NODES * C_HID / 4];   // GEMM1 out (f32)
__device__ float4 g_h2 [N_NODES * C_OUT / 4];   // GEMM2 out (f32)
__device__ float  g_dinv[N_NODES];

// CSR-by-dst edge structure (built per launch)
__device__ int    g_deg   [N_NODES];
__device__ int    g_eoff  [N_NODES + 1];
__device__ int    g_cursor[N_NODES];
__device__ int    g_esrc  [E_MAX];
__device__ float  g_ew    [E_MAX];

// bf16 hi/lo splits (z and weights only; x converts inline in GEMM1)
__device__ __nv_bfloat16 g_zhi [N_NODES * C_HID];
__device__ __nv_bfloat16 g_zlo [N_NODES * C_HID];
__device__ __nv_bfloat16 g_w1hi[C_IN * C_HID];
__device__ __nv_bfloat16 g_w1lo[C_IN * C_HID];
__device__ __nv_bfloat16 g_w2hi[C_HID * C_OUT];
__device__ __nv_bfloat16 g_w2lo[C_HID * C_OUT];

// ---------------------------------------------------------------------------
// degree histogram / dinv
// ---------------------------------------------------------------------------
__global__ void zero_deg_kernel() {
    int i = blockIdx.x * blockDim.x + threadIdx.x;
    if (i < N_NODES) g_deg[i] = 0;
}

__global__ void deg_accum_kernel(const int* __restrict__ dst, int E) {
    int i = blockIdx.x * blockDim.x + threadIdx.x;
    if (i < E) {
        unsigned d = (unsigned)dst[i];
        if (d < N_NODES) atomicAdd(&g_deg[d], 1);
    }
}

__global__ void dinv_finalize_kernel() {
    int i = blockIdx.x * blockDim.x + threadIdx.x;
    if (i < N_NODES) g_dinv[i] = rsqrtf((float)(g_deg[i] + 1));  // +1 self-loop
}

// ---------------------------------------------------------------------------
// Single-block exclusive scan of g_deg -> g_eoff / g_cursor
// ---------------------------------------------------------------------------
#define SCAN_T 1024
__global__ __launch_bounds__(SCAN_T) void scan_kernel() {
    __shared__ int sh[SCAN_T];
    const int tid = threadIdx.x;
    const int PER = (N_NODES + SCAN_T - 1) / SCAN_T;
    const int base = tid * PER;
    int s = 0;
    for (int j = 0; j < PER; ++j) {
        int i = base + j;
        if (i < N_NODES) s += g_deg[i];
    }
    sh[tid] = s;
    __syncthreads();
    for (int off = 1; off < SCAN_T; off <<= 1) {
        int v = (tid >= off) ? sh[tid - off] : 0;
        __syncthreads();
        sh[tid] += v;
        __syncthreads();
    }
    int running = sh[tid] - s;
    for (int j = 0; j < PER; ++j) {
        int i = base + j;
        if (i < N_NODES) {
            g_eoff[i]   = running;
            g_cursor[i] = running;
            running += g_deg[i];
        }
    }
    if (tid == SCAN_T - 1) g_eoff[N_NODES] = sh[SCAN_T - 1];
}

// ---------------------------------------------------------------------------
// Bucket edges by dst; precompute norm weight
// ---------------------------------------------------------------------------
__global__ void bucket_kernel(const int* __restrict__ src,
                              const int* __restrict__ dst, int E) {
    int e = blockIdx.x * blockDim.x + threadIdx.x;
    if (e >= E) return;
    unsigned s = (unsigned)src[e];
    unsigned d = (unsigned)dst[e];
    if (s >= N_NODES || d >= N_NODES) return;
    int pos = atomicAdd(&g_cursor[d], 1);
    if (pos < E_MAX) {
        g_esrc[pos] = (int)s;
        g_ew[pos]   = g_dinv[s] * g_dinv[d];
    }
}

// ---------------------------------------------------------------------------
// f32 -> (hi, lo) bf16 split for weights.  which: 1=W1, 2=W2
// ---------------------------------------------------------------------------
__global__ void split_kernel(const float* __restrict__ in, int n4, int which) {
    __nv_bfloat16* hi = (which == 1) ? g_w1hi : g_w2hi;
    __nv_bfloat16* lo = (which == 1) ? g_w1lo : g_w2lo;
    int i = blockIdx.x * blockDim.x + threadIdx.x;
    if (i >= n4) return;
    float4 v = ((const float4*)in)[i];
    float f[4] = {v.x, v.y, v.z, v.w};
    __nv_bfloat16 h[4], l[4];
#pragma unroll
    for (int j = 0; j < 4; ++j) {
        h[j] = __float2bfloat16_rn(f[j]);
        l[j] = __float2bfloat16_rn(f[j] - __bfloat162float(h[j]));
    }
    ((__nv_bfloat162*)hi)[2 * i]     = __nv_bfloat162(h[0], h[1]);
    ((__nv_bfloat162*)hi)[2 * i + 1] = __nv_bfloat162(h[2], h[3]);
    ((__nv_bfloat162*)lo)[2 * i]     = __nv_bfloat162(l[0], l[1]);
    ((__nv_bfloat162*)lo)[2 * i + 1] = __nv_bfloat162(l[2], l[3]);
}

// ---------------------------------------------------------------------------
// PTX helpers
// ---------------------------------------------------------------------------
__device__ __forceinline__ void mma_bf16(float c[4], const uint32_t a[4],
                                         const uint32_t b[2]) {
    asm volatile(
        "mma.sync.aligned.m16n8k16.row.col.f32.bf16.bf16.f32 "
        "{%0,%1,%2,%3}, {%4,%5,%6,%7}, {%8,%9}, {%0,%1,%2,%3};\n"
        : "+f"(c[0]), "+f"(c[1]), "+f"(c[2]), "+f"(c[3])
        : "r"(a[0]), "r"(a[1]), "r"(a[2]), "r"(a[3]), "r"(b[0]), "r"(b[1]));
}

__device__ __forceinline__ void ldsm_x4(uint32_t r[4], uint32_t addr) {
    asm volatile("ldmatrix.sync.aligned.m8n8.x4.shared.b16 {%0,%1,%2,%3}, [%4];"
                 : "=r"(r[0]), "=r"(r[1]), "=r"(r[2]), "=r"(r[3]) : "r"(addr));
}

__device__ __forceinline__ void ldsm_x4_t(uint32_t r[4], uint32_t addr) {
    asm volatile("ldmatrix.sync.aligned.m8n8.x4.trans.shared.b16 {%0,%1,%2,%3}, [%4];"
                 : "=r"(r[0]), "=r"(r[1]), "=r"(r[2]), "=r"(r[3]) : "r"(addr));
}

__device__ __forceinline__ void cp_async16(uint32_t saddr, const void* g, int srcbytes) {
    asm volatile("cp.async.cg.shared.global [%0], [%1], 16, %2;"
                 :: "r"(saddr), "l"(g), "r"(srcbytes));
}

__device__ __forceinline__ void sts_v2(uint32_t saddr, uint32_t a, uint32_t b) {
    asm volatile("st.shared.v2.b32 [%0], {%1, %2};" :: "r"(saddr), "r"(a), "r"(b));
}

__device__ __forceinline__ uint32_t pack_bf16x2(__nv_bfloat16 a, __nv_bfloat16 b) {
    __nv_bfloat162 p(a, b);
    return *(uint32_t*)&p;
}

// ---------------------------------------------------------------------------
// GEMM1: g_h1[M,256] = x[M,1536] @ W1-split.  Inline f32->bf16 hi/lo A split.
// BM=64, BN=256, BK=32. A: LDG f32 -> regs -> convert -> STS (pipelined).
// B: cp.async double-buffered from pre-split weights.
// ---------------------------------------------------------------------------
__global__ __launch_bounds__(256, 2) void mma_gemm1(const float* __restrict__ X, int M) {
    constexpr int BN = C_HID, K = C_IN, BM = 64, BK = 32;
    constexpr int AST  = 80;
    constexpr int BROW = BN * 2 + 16;
    constexpr int A_STAGE = 2 * BM * AST;
    constexpr int B_STAGE = 2 * BK * BROW;
    constexpr int NT = BN / 32;         // 8
    constexpr int KT = K / BK;          // 48

    extern __shared__ char smem[];
    uint32_t sA = (uint32_t)__cvta_generic_to_shared(smem);
    uint32_t sB = sA + 2 * A_STAGE;

    const int tid = threadIdx.x, lane = tid & 31, warp = tid >> 5;
    const int warpM = warp & 1, warpN = warp >> 1;
    const int g = lane >> 2, t4 = lane & 3;
    const int rowBase = blockIdx.x * BM;

    // A staging coordinates: 512 float4-chunks per tile, 2 per thread
    const int ar0 = tid >> 3,              ac0 = tid & 7;          // chunk tid
    const int ar1 = (tid + 256) >> 3,      ac1 = (tid + 256) & 7;  // chunk tid+256

    float4 areg[2];

    auto ldgA = [&](int kt) {
        const int k0 = kt * BK;
        int gr0 = rowBase + ar0;
        int gr1 = rowBase + ar1;
        areg[0] = (gr0 < M) ? *(const float4*)(X + (size_t)gr0 * K + k0 + ac0 * 4)
                            : make_float4(0.f, 0.f, 0.f, 0.f);
        areg[1] = (gr1 < M) ? *(const float4*)(X + (size_t)gr1 * K + k0 + ac1 * 4)
                            : make_float4(0.f, 0.f, 0.f, 0.f);
    };

    auto stsA = [&](int s) {
#pragma unroll
        for (int it = 0; it < 2; ++it) {
            int row = it ? ar1 : ar0;
            int c4  = it ? ac1 : ac0;
            float f[4] = {areg[it].x, areg[it].y, areg[it].z, areg[it].w};
            __nv_bfloat16 h[4], l[4];
#pragma unroll
            for (int j = 0; j < 4; ++j) {
                h[j] = __float2bfloat16_rn(f[j]);
                l[j] = __float2bfloat16_rn(f[j] - __bfloat162float(h[j]));
            }
            uint32_t base = sA + s * A_STAGE + row * AST + c4 * 8;
            sts_v2(base,                 pack_bf16x2(h[0], h[1]), pack_bf16x2(h[2], h[3]));
            sts_v2(base + BM * AST,      pack_bf16x2(l[0], l[1]), pack_bf16x2(l[2], l[3]));
        }
    };

    auto stageB = [&](int kt, int s) {
        const int k0 = kt * BK;
        constexpr int BCH = 2 * BK * (BN / 8);   // 2048
#pragma unroll
        for (int it = 0; it < BCH / 256; ++it) {
            int c = tid + it * 256;
            int hl = c / (BCH / 2);
            int cc = c % (BCH / 2);
            int row = cc / (BN / 8), nc = cc % (BN / 8);
            const __nv_bfloat16* src = (hl ? g_w1lo : g_w1hi) + (size_t)(k0 + row) * BN + nc * 8;
            cp_async16(sB + s * B_STAGE + hl * (BK * BROW) + row * BROW + nc * 16, src, 16);
        }
        asm volatile("cp.async.commit_group;");
    };

    float acc[2][NT][4] = {};

    ldgA(0);
    stageB(0, 0);
    for (int kt = 0; kt < KT; ++kt) {
        const int s = kt & 1;
        stsA(s);
        if (kt + 1 < KT) {
            ldgA(kt + 1);
            stageB(kt + 1, s ^ 1);
            asm volatile("cp.async.wait_group 1;");
        } else {
            asm volatile("cp.async.wait_group 0;");
        }
        __syncthreads();

        const int q = lane >> 3;
#pragma unroll
        for (int ks = 0; ks < 2; ++ks) {
            uint32_t a[2][2][4];
#pragma unroll
            for (int mi = 0; mi < 2; ++mi) {
                int row  = warpM * 32 + mi * 16 + (q & 1) * 8 + (lane & 7);
                int colb = (ks * 16 + (q >> 1) * 8) * 2;
#pragma unroll
                for (int hl = 0; hl < 2; ++hl)
                    ldsm_x4(a[mi][hl], sA + s * A_STAGE + hl * (BM * AST) + row * AST + colb);
            }
#pragma unroll
            for (int np = 0; np < NT / 2; ++np) {
                uint32_t bq[2][4];
                int krow = ks * 16 + (q & 1) * 8 + (lane & 7);
                int ncol = warpN * (BN / 4) + np * 16 + (q >> 1) * 8;
#pragma unroll
                for (int hl = 0; hl < 2; ++hl)
                    ldsm_x4_t(bq[hl], sB + s * B_STAGE + hl * (BK * BROW) + krow * BROW + ncol * 2);
#pragma unroll
                for (int half = 0; half < 2; ++half) {
                    uint32_t bh[2] = {bq[0][half * 2], bq[0][half * 2 + 1]};
                    uint32_t bl[2] = {bq[1][half * 2], bq[1][half * 2 + 1]};
                    const int nt = np * 2 + half;
#pragma unroll
                    for (int mi = 0; mi < 2; ++mi) {
                        mma_bf16(acc[mi][nt], a[mi][0], bh);
                        mma_bf16(acc[mi][nt], a[mi][0], bl);
                        mma_bf16(acc[mi][nt], a[mi][1], bh);
                    }
                }
            }
        }
        __syncthreads();
    }

    float* C = (float*)g_h1;
#pragma unroll
    for (int mi = 0; mi < 2; ++mi)
#pragma unroll
        for (int nt = 0; nt < NT; ++nt) {
            int col = warpN * (BN / 4) + nt * 8 + t4 * 2;
            int r0  = rowBase + warpM * 32 + mi * 16 + g;
            if (r0 < M)
                *(float2*)(C + (size_t)r0 * BN + col) = make_float2(acc[mi][nt][0], acc[mi][nt][1]);
            int r1 = r0 + 8;
            if (r1 < M)
                *(float2*)(C + (size_t)r1 * BN + col) = make_float2(acc[mi][nt][2], acc[mi][nt][3]);
        }
}

// ---------------------------------------------------------------------------
// GEMM2: g_h2[M,128] = z-split @ W2-split (cp.async path, pre-split inputs)
// ---------------------------------------------------------------------------
__global__ __launch_bounds__(256, 2) void mma_gemm2(int M) {
    constexpr int BN = C_OUT, K = C_HID, BM = 64, BK = 32;
    constexpr int AST  = 80;
    constexpr int BROW = BN * 2 + 16;
    constexpr int A_STAGE = 2 * BM * AST;
    constexpr int B_STAGE = 2 * BK * BROW;
    constexpr int NT = BN / 32;         // 4
    constexpr int KT = K / BK;          // 8

    extern __shared__ char smem[];
    uint32_t sA = (uint32_t)__cvta_generic_to_shared(smem);
    uint32_t sB = sA + 2 * A_STAGE;

    const int tid = threadIdx.x, lane = tid & 31, warp = tid >> 5;
    const int warpM = warp & 1, warpN = warp >> 1;
    const int g = lane >> 2, t4 = lane & 3;
    const int rowBase = blockIdx.x * BM;

    float acc[2][NT][4] = {};

    auto stage = [&](int kt, int s) {
        const int k0 = kt * BK;
#pragma unroll
        for (int it = 0; it < 2; ++it) {
            int c = tid + it * 256;
            int hl = c >> 8, cc = c & 255;
            int row = cc >> 2, kc = cc & 3;
            int grow = rowBase + row;
            int sz = (grow < M) ? 16 : 0;
            if (grow >= M) grow = M - 1;
            const __nv_bfloat16* src = (hl ? g_zlo : g_zhi) + (size_t)grow * K + k0 + kc * 8;
            cp_async16(sA + s * A_STAGE + hl * (BM * AST) + row * AST + kc * 16, src, sz);
        }
        constexpr int BCH = 2 * BK * (BN / 8);
#pragma unroll
        for (int it = 0; it < BCH / 256; ++it) {
            int c = tid + it * 256;
            int hl = c / (BCH / 2);
            int cc = c % (BCH / 2);
            int row = cc / (BN / 8), nc = cc % (BN / 8);
            const __nv_bfloat16* src = (hl ? g_w2lo : g_w2hi) + (size_t)(k0 + row) * BN + nc * 8;
            cp_async16(sB + s * B_STAGE + hl * (BK * BROW) + row * BROW + nc * 16, src, 16);
        }
        asm volatile("cp.async.commit_group;");
    };

    stage(0, 0);
    for (int kt = 0; kt < KT; ++kt) {
        const int s = kt & 1;
        if (kt + 1 < KT) {
            stage(kt + 1, s ^ 1);
            asm volatile("cp.async.wait_group 1;");
        } else {
            asm volatile("cp.async.wait_group 0;");
        }
        __syncthreads();

        const int q = lane >> 3;
#pragma unroll
        for (int ks = 0; ks < 2; ++ks) {
            uint32_t a[2][2][4];
#pragma unroll
            for (int mi = 0; mi < 2; ++mi) {
                int row  = warpM * 32 + mi * 16 + (q & 1) * 8 + (lane & 7);
                int colb = (ks * 16 + (q >> 1) * 8) * 2;
#pragma unroll
                for (int hl = 0; hl < 2; ++hl)
                    ldsm_x4(a[mi][hl], sA + s * A_STAGE + hl * (BM * AST) + row * AST + colb);
            }
#pragma unroll
            for (int np = 0; np < NT / 2; ++np) {
                uint32_t bq[2][4];
                int krow = ks * 16 + (q & 1) * 8 + (lane & 7);
                int ncol = warpN * (BN / 4) + np * 16 + (q >> 1) * 8;
#pragma unroll
                for (int hl = 0; hl < 2; ++hl)
                    ldsm_x4_t(bq[hl], sB + s * B_STAGE + hl * (BK * BROW) + krow * BROW + ncol * 2);
#pragma unroll
                for (int half = 0; half < 2; ++half) {
                    uint32_t bh[2] = {bq[0][half * 2], bq[0][half * 2 + 1]};
                    uint32_t bl[2] = {bq[1][half * 2], bq[1][half * 2 + 1]};
                    const int nt = np * 2 + half;
#pragma unroll
                    for (int mi = 0; mi < 2; ++mi) {
                        mma_bf16(acc[mi][nt], a[mi][0], bh);
                        mma_bf16(acc[mi][nt], a[mi][0], bl);
                        mma_bf16(acc[mi][nt], a[mi][1], bh);
                    }
                }
            }
        }
        __syncthreads();
    }

    float* C = (float*)g_h2;
#pragma unroll
    for (int mi = 0; mi < 2; ++mi)
#pragma unroll
        for (int nt = 0; nt < NT; ++nt) {
            int col = warpN * (BN / 4) + nt * 8 + t4 * 2;
            int r0  = rowBase + warpM * 32 + mi * 16 + g;
            if (r0 < M)
                *(float2*)(C + (size_t)r0 * BN + col) = make_float2(acc[mi][nt][0], acc[mi][nt][1]);
            int r1 = r0 + 8;
            if (r1 < M)
                *(float2*)(C + (size_t)r1 * BN + col) = make_float2(acc[mi][nt][2], acc[mi][nt][3]);
        }
}

// ---------------------------------------------------------------------------
// Layer-1 gather aggregation (warp per node, C=256) + bias + relu + bf16 split
// ---------------------------------------------------------------------------
__global__ __launch_bounds__(256) void gather_agg1_kernel(const float* __restrict__ b1) {
    int node = (blockIdx.x * blockDim.x + threadIdx.x) >> 5;
    int lane = threadIdx.x & 31;
    if (node >= N_NODES) return;

    const float4* h = g_h1;
    float di = g_dinv[node];
    float ws = di * di;
    size_t rb = (size_t)node * 64;
    float4 a0 = h[rb + lane];
    float4 a1 = h[rb + 32 + lane];
    a0.x *= ws; a0.y *= ws; a0.z *= ws; a0.w *= ws;
    a1.x *= ws; a1.y *= ws; a1.z *= ws; a1.w *= ws;

    int beg = g_eoff[node], end = g_eoff[node + 1];
    int k = beg;
    for (; k + 2 <= end; k += 2) {
        int s0 = g_esrc[k], s1 = g_esrc[k + 1];
        float w0 = g_ew[k], w1 = g_ew[k + 1];
        size_t r0 = (size_t)s0 * 64, r1 = (size_t)s1 * 64;
        float4 v00 = h[r0 + lane], v01 = h[r0 + 32 + lane];
        float4 v10 = h[r1 + lane], v11 = h[r1 + 32 + lane];
        a0.x += v00.x * w0; a0.y += v00.y * w0; a0.z += v00.z * w0; a0.w += v00.w * w0;
        a1.x += v01.x * w0; a1.y += v01.y * w0; a1.z += v01.z * w0; a1.w += v01.w * w0;
        a0.x += v10.x * w1; a0.y += v10.y * w1; a0.z += v10.z * w1; a0.w += v10.w * w1;
        a1.x += v11.x * w1; a1.y += v11.y * w1; a1.z += v11.z * w1; a1.w += v11.w * w1;
    }
    if (k < end) {
        int s0 = g_esrc[k]; float w0 = g_ew[k];
        size_t r0 = (size_t)s0 * 64;
        float4 v00 = h[r0 + lane], v01 = h[r0 + 32 + lane];
        a0.x += v00.x * w0; a0.y += v00.y * w0; a0.z += v00.z * w0; a0.w += v00.w * w0;
        a1.x += v01.x * w0; a1.y += v01.y * w0; a1.z += v01.z * w0; a1.w += v01.w * w0;
    }

    float4 bb0 = ((const float4*)b1)[lane];
    float4 bb1 = ((const float4*)b1)[lane + 32];
    float f0[4] = {fmaxf(a0.x + bb0.x, 0.f), fmaxf(a0.y + bb0.y, 0.f),
                   fmaxf(a0.z + bb0.z, 0.f), fmaxf(a0.w + bb0.w, 0.f)};
    float f1[4] = {fmaxf(a1.x + bb1.x, 0.f), fmaxf(a1.y + bb1.y, 0.f),
                   fmaxf(a1.z + bb1.z, 0.f), fmaxf(a1.w + bb1.w, 0.f)};

    __nv_bfloat162* zh = (__nv_bfloat162*)(g_zhi + (size_t)node * C_HID);
    __nv_bfloat162* zl = (__nv_bfloat162*)(g_zlo + (size_t)node * C_HID);
#pragma unroll
    for (int half = 0; half < 2; ++half) {
        float* f = half ? f1 : f0;
        int idx = 2 * (lane + half * 32);
        __nv_bfloat16 h0 = __float2bfloat16_rn(f[0]);
        __nv_bfloat16 h1v = __float2bfloat16_rn(f[1]);
        __nv_bfloat16 h2v = __float2bfloat16_rn(f[2]);
        __nv_bfloat16 h3 = __float2bfloat16_rn(f[3]);
        zh[idx]     = __nv_bfloat162(h0, h1v);
        zh[idx + 1] = __nv_bfloat162(h2v, h3);
        zl[idx]     = __nv_bfloat162(__float2bfloat16_rn(f[0] - __bfloat162float(h0)),
                                     __float2bfloat16_rn(f[1] - __bfloat162float(h1v)));
        zl[idx + 1] = __nv_bfloat162(__float2bfloat16_rn(f[2] - __bfloat162float(h2v)),
                                     __float2bfloat16_rn(f[3] - __bfloat162float(h3)));
    }
}

// ---------------------------------------------------------------------------
// Layer-2 gather aggregation + bias + row-normalize (warp per node, C=128)
// ---------------------------------------------------------------------------
__global__ __launch_bounds__(256) void gather_agg2_kernel(const float* __restrict__ b2,
                                                          float* __restrict__ out) {
    int node = (blockIdx.x * blockDim.x + threadIdx.x) >> 5;
    int lane = threadIdx.x & 31;
    if (node >= N_NODES) return;

    const float4* h = g_h2;
    float di = g_dinv[node];
    float ws = di * di;
    float4 a = h[(size_t)node * 32 + lane];
    a.x *= ws; a.y *= ws; a.z *= ws; a.w *= ws;

    int beg = g_eoff[node], end = g_eoff[node + 1];
    int k = beg;
    for (; k + 2 <= end; k += 2) {
        int s0 = g_esrc[k], s1 = g_esrc[k + 1];
        float w0 = g_ew[k], w1 = g_ew[k + 1];
        float4 v0 = h[(size_t)s0 * 32 + lane];
        float4 v1 = h[(size_t)s1 * 32 + lane];
        a.x += v0.x * w0; a.y += v0.y * w0; a.z += v0.z * w0; a.w += v0.w * w0;
        a.x += v1.x * w1; a.y += v1.y * w1; a.z += v1.z * w1; a.w += v1.w * w1;
    }
    if (k < end) {
        int s0 = g_esrc[k]; float w0 = g_ew[k];
        float4 v0 = h[(size_t)s0 * 32 + lane];
        a.x += v0.x * w0; a.y += v0.y * w0; a.z += v0.z * w0; a.w += v0.w * w0;
    }

    float4 bb = ((const float4*)b2)[lane];
    a.x += bb.x; a.y += bb.y; a.z += bb.z; a.w += bb.w;
    float s = a.x * a.x + a.y * a.y + a.z * a.z + a.w * a.w;
#pragma unroll
    for (int m = 16; m > 0; m >>= 1) s += __shfl_xor_sync(0xffffffffu, s, m);
    float inv = 1.0f / fmaxf(sqrtf(s), 1e-12f);
    a.x *= inv; a.y *= inv; a.z *= inv; a.w *= inv;
    ((float4*)out)[(size_t)node * 32 + lane] = a;
}

// ---------------------------------------------------------------------------
// Launch
// ---------------------------------------------------------------------------
extern "C" void kernel_launch(void* const* d_in, const int* in_sizes, int n_in,
                              void* d_out, int out_size) {
    const float* x  = (const float*)d_in[0];
    const int*   ei = (const int*)d_in[1];      // int32
    const float* W1 = (const float*)d_in[2];
    const float* b1 = (const float*)d_in[3];
    const float* W2 = (const float*)d_in[4];
    const float* b2 = (const float*)d_in[5];
    float* out = (float*)d_out;

    const int E = in_sizes[1] / 2;
    const int* src = ei;
    const int* dst = ei + E;

    constexpr int SMEM0 = 2 * (2 * 64 * 80) + 2 * (2 * 32 * (256 * 2 + 16));  // 88064
    constexpr int SMEM1 = 2 * (2 * 64 * 80) + 2 * (2 * 32 * (128 * 2 + 16));  // 55296
    static bool attr_done = false;
    if (!attr_done) {
        cudaFuncSetAttribute(mma_gemm1, cudaFuncAttributeMaxDynamicSharedMemorySize, SMEM0);
        cudaFuncSetAttribute(mma_gemm2, cudaFuncAttributeMaxDynamicSharedMemorySize, SMEM1);
        attr_done = true;
    }

    // 0) bf16 splits for weights only (x converts inline in GEMM1)
    split_kernel<<<(C_IN * C_HID / 4 + 255) / 256, 256>>>(W1, C_IN * C_HID / 4, 1);
    split_kernel<<<(C_HID * C_OUT / 4 + 255) / 256, 256>>>(W2, C_HID * C_OUT / 4, 2);

    // 1) degree histogram -> dinv, CSR offsets, bucketed edges
    zero_deg_kernel<<<(N_NODES + 255) / 256, 256>>>();
    deg_accum_kernel<<<(E + 255) / 256, 256>>>(dst, E);
    dinv_finalize_kernel<<<(N_NODES + 255) / 256, 256>>>();
    scan_kernel<<<1, SCAN_T>>>();
    bucket_kernel<<<(E + 255) / 256, 256>>>(src, dst, E);

    // 2) g_h1 = x @ W1 (inline split)
    mma_gemm1<<<(N_NODES + 63) / 64, 256, SMEM0>>>(x, N_NODES);

    // 3) layer-1 aggregation + bias + relu + bf16 split (fused)
    gather_agg1_kernel<<<(N_NODES * 32 + 255) / 256, 256>>>(b1);

    // 4) g_h2 = z @ W2
    mma_gemm2<<<(N_NODES + 63) / 64, 256, SMEM1>>>(N_NODES);

    // 5) layer-2 aggregation + bias + normalize -> out (fused)
    gather_agg2_kernel<<<(N_NODES * 32 + 255) / 256, 256>>>(b2, out);
}

// round 9
// speedup vs baseline: 3.7826x; 1.0198x over previous
#include <cuda_runtime.h>
#include <cuda_bf16.h>
#include <stdint.h>

// Problem constants (from reference setup_inputs)
#define N_NODES 50000
#define C_IN    1536
#define C_HID   256
#define C_OUT   128
#define E_MAX   1600000

// ---------------------------------------------------------------------------
// Device-global scratch (no allocation allowed)
// ---------------------------------------------------------------------------
__device__ float4 g_h1 [N_NODES * C_HID / 4];   // GEMM1 out (f32)
__device__ float4 g_h2 [N_NODES * C_OUT / 4];   // GEMM2 out (f32)
__device__ float  g_dinv[N_NODES];

// CSR-by-dst edge structure (built per launch)
__device__ int    g_deg   [N_NODES];
__device__ int    g_eoff  [N_NODES + 1];
__device__ int    g_cursor[N_NODES];
__device__ int    g_esrc  [E_MAX];
__device__ float  g_ew    [E_MAX];

// bf16 hi/lo splits (K-major weights; z from fused agg1)
__device__ __nv_bfloat16 g_zhi [N_NODES * C_HID];
__device__ __nv_bfloat16 g_zlo [N_NODES * C_HID];
__device__ __nv_bfloat16 g_w1hi[C_IN * C_HID];
__device__ __nv_bfloat16 g_w1lo[C_IN * C_HID];
__device__ __nv_bfloat16 g_w2hi[C_HID * C_OUT];
__device__ __nv_bfloat16 g_w2lo[C_HID * C_OUT];

// ---------------------------------------------------------------------------
// Weight splits: W1 and W2 in ONE launch (f32 -> hi/lo bf16, K-major)
// ---------------------------------------------------------------------------
#define W1_N4 (C_IN * C_HID / 4)    // 98304
#define W2_N4 (C_HID * C_OUT / 4)   // 8192

__global__ void split_weights_kernel(const float* __restrict__ W1,
                                     const float* __restrict__ W2) {
    int i = blockIdx.x * blockDim.x + threadIdx.x;
    if (i >= W1_N4 + W2_N4) return;
    const float4* in;
    __nv_bfloat16 *hi, *lo;
    int j;
    if (i < W1_N4) { in = (const float4*)W1; hi = g_w1hi; lo = g_w1lo; j = i; }
    else           { in = (const float4*)W2; hi = g_w2hi; lo = g_w2lo; j = i - W1_N4; }
    float4 v = in[j];
    float f[4] = {v.x, v.y, v.z, v.w};
    __nv_bfloat16 h[4], l[4];
#pragma unroll
    for (int t = 0; t < 4; ++t) {
        h[t] = __float2bfloat16_rn(f[t]);
        l[t] = __float2bfloat16_rn(f[t] - __bfloat162float(h[t]));
    }
    ((__nv_bfloat162*)hi)[2 * j]     = __nv_bfloat162(h[0], h[1]);
    ((__nv_bfloat162*)hi)[2 * j + 1] = __nv_bfloat162(h[2], h[3]);
    ((__nv_bfloat162*)lo)[2 * j]     = __nv_bfloat162(l[0], l[1]);
    ((__nv_bfloat162*)lo)[2 * j + 1] = __nv_bfloat162(l[2], l[3]);
}

// ---------------------------------------------------------------------------
// degree histogram
// ---------------------------------------------------------------------------
__global__ void zero_deg_kernel() {
    int i = blockIdx.x * blockDim.x + threadIdx.x;
    if (i < N_NODES) g_deg[i] = 0;
}

__global__ void deg_accum_kernel(const int* __restrict__ dst, int E) {
    int i = blockIdx.x * blockDim.x + threadIdx.x;
    if (i < E) {
        unsigned d = (unsigned)dst[i];
        if (d < N_NODES) atomicAdd(&g_deg[d], 1);
    }
}

// ---------------------------------------------------------------------------
// Single-block exclusive scan of g_deg -> g_eoff / g_cursor; also dinv
// ---------------------------------------------------------------------------
#define SCAN_T 1024
__global__ __launch_bounds__(SCAN_T) void scan_kernel() {
    __shared__ int sh[SCAN_T];
    const int tid = threadIdx.x;
    const int PER = (N_NODES + SCAN_T - 1) / SCAN_T;
    const int base = tid * PER;
    int s = 0;
    for (int j = 0; j < PER; ++j) {
        int i = base + j;
        if (i < N_NODES) s += g_deg[i];
    }
    sh[tid] = s;
    __syncthreads();
    for (int off = 1; off < SCAN_T; off <<= 1) {
        int v = (tid >= off) ? sh[tid - off] : 0;
        __syncthreads();
        sh[tid] += v;
        __syncthreads();
    }
    int running = sh[tid] - s;
    for (int j = 0; j < PER; ++j) {
        int i = base + j;
        if (i < N_NODES) {
            int d = g_deg[i];
            g_eoff[i]   = running;
            g_cursor[i] = running;
            g_dinv[i]   = rsqrtf((float)(d + 1));   // +1 self-loop
            running += d;
        }
    }
    if (tid == SCAN_T - 1) g_eoff[N_NODES] = sh[SCAN_T - 1];
}

__global__ void bucket_kernel(const int* __restrict__ src,
                              const int* __restrict__ dst, int E) {
    int e = blockIdx.x * blockDim.x + threadIdx.x;
    if (e >= E) return;
    unsigned s = (unsigned)src[e];
    unsigned d = (unsigned)dst[e];
    if (s >= N_NODES || d >= N_NODES) return;
    int pos = atomicAdd(&g_cursor[d], 1);
    if (pos < E_MAX) {
        g_esrc[pos] = (int)s;
        g_ew[pos]   = g_dinv[s] * g_dinv[d];
    }
}

// ---------------------------------------------------------------------------
// PTX helpers
// ---------------------------------------------------------------------------
__device__ __forceinline__ void mma_bf16(float c[4], const uint32_t a[4],
                                         const uint32_t b[2]) {
    asm volatile(
        "mma.sync.aligned.m16n8k16.row.col.f32.bf16.bf16.f32 "
        "{%0,%1,%2,%3}, {%4,%5,%6,%7}, {%8,%9}, {%0,%1,%2,%3};\n"
        : "+f"(c[0]), "+f"(c[1]), "+f"(c[2]), "+f"(c[3])
        : "r"(a[0]), "r"(a[1]), "r"(a[2]), "r"(a[3]), "r"(b[0]), "r"(b[1]));
}

__device__ __forceinline__ void ldsm_x4(uint32_t r[4], uint32_t addr) {
    asm volatile("ldmatrix.sync.aligned.m8n8.x4.shared.b16 {%0,%1,%2,%3}, [%4];"
                 : "=r"(r[0]), "=r"(r[1]), "=r"(r[2]), "=r"(r[3]) : "r"(addr));
}

__device__ __forceinline__ void ldsm_x4_t(uint32_t r[4], uint32_t addr) {
    asm volatile("ldmatrix.sync.aligned.m8n8.x4.trans.shared.b16 {%0,%1,%2,%3}, [%4];"
                 : "=r"(r[0]), "=r"(r[1]), "=r"(r[2]), "=r"(r[3]) : "r"(addr));
}

__device__ __forceinline__ void cp_async16(uint32_t saddr, const void* g, int srcbytes) {
    asm volatile("cp.async.cg.shared.global [%0], [%1], 16, %2;"
                 :: "r"(saddr), "l"(g), "r"(srcbytes));
}

__device__ __forceinline__ void sts_v2(uint32_t saddr, uint32_t a, uint32_t b) {
    asm volatile("st.shared.v2.b32 [%0], {%1, %2};" :: "r"(saddr), "r"(a), "r"(b));
}

__device__ __forceinline__ uint32_t pack_bf16x2(__nv_bfloat16 a, __nv_bfloat16 b) {
    __nv_bfloat162 p(a, b);
    return *(uint32_t*)&p;
}

// ---------------------------------------------------------------------------
// Unified split-bf16 tensor-core GEMM.  C[M,BNF] = A[M,K] @ B[K,BNF].
// 3-term: Ah*Bh + Ah*Bl + Al*Bh.  Tile: BM = MI*32, BN per CTA, BK=32.
// MODE 0: A = X (f32, inline hi/lo split via LDG->STS), B = W1 splits, C = g_h1
// MODE 1: A = z splits (cp.async),                      B = W2 splits, C = g_h2
// ---------------------------------------------------------------------------
template <int MI, int BN, int KDIM, int MODE>
__global__ __launch_bounds__(256, 2) void mma_gemm(const float* __restrict__ X, int M) {
    constexpr int BM   = MI * 32;
    constexpr int BK   = 32;
    constexpr int AST  = 80;                   // A smem row stride (bytes)
    constexpr int BROW = BN * 2 + 16;          // B smem row stride (bytes)
    constexpr int A_STAGE = 2 * BM * AST;      // hi+lo
    constexpr int B_STAGE = 2 * BK * BROW;
    constexpr int NT  = BN / 32;               // n8-tile pairs per warp
    constexpr int KT  = KDIM / BK;
    constexpr int BNF = MODE ? C_OUT : C_HID;  // full width of B rows / C rows

    const __nv_bfloat16* Bh = MODE ? g_w2hi : g_w1hi;
    const __nv_bfloat16* Bl = MODE ? g_w2lo : g_w1lo;
    float*               C  = MODE ? (float*)g_h2 : (float*)g_h1;

    extern __shared__ char smem[];
    uint32_t sA = (uint32_t)__cvta_generic_to_shared(smem);
    uint32_t sB = sA + 2 * A_STAGE;

    const int tid = threadIdx.x, lane = tid & 31, warp = tid >> 5;
    const int warpM = warp & 1, warpN = warp >> 1;
    const int g = lane >> 2, t4 = lane & 3;
    const int rowBase = blockIdx.x * BM;
    const int colBase = blockIdx.y * BN;

    float acc[MI][NT][4] = {};

    // MODE 0 A-staging registers (f32 chunks; BM*8 chunks total, /256 per thread)
    constexpr int AC = (BM * 8) / 256;         // 2 for BM=64, 1 for BM=32
    float4 areg[AC > 0 ? AC : 1];

    auto ldgA = [&](int kt) {
        if constexpr (MODE == 0) {
            const int k0 = kt * BK;
#pragma unroll
            for (int it = 0; it < AC; ++it) {
                int idx = tid + it * 256;
                int row = idx >> 3;
                int c4  = idx & 7;             // 8B unit within 32-elem row
                int grow = rowBase + row;
                if (grow >= M) grow = M - 1;
                areg[it] = *(const float4*)(X + (size_t)grow * KDIM + k0 + c4 * 4);
            }
        }
    };

    auto stsA = [&](int s) {
        if constexpr (MODE == 0) {
#pragma unroll
            for (int it = 0; it < AC; ++it) {
                int idx = tid + it * 256;
                int row = idx >> 3;
                int c4  = idx & 7;
                float f[4] = {areg[it].x, areg[it].y, areg[it].z, areg[it].w};
                __nv_bfloat16 h[4], l[4];
#pragma unroll
                for (int j = 0; j < 4; ++j) {
                    h[j] = __float2bfloat16_rn(f[j]);
                    l[j] = __float2bfloat16_rn(f[j] - __bfloat162float(h[j]));
                }
                uint32_t base = sA + s * A_STAGE + row * AST + c4 * 8;
                sts_v2(base,            pack_bf16x2(h[0], h[1]), pack_bf16x2(h[2], h[3]));
                sts_v2(base + BM * AST, pack_bf16x2(l[0], l[1]), pack_bf16x2(l[2], l[3]));
            }
        }
    };

    auto stageA_async = [&](int kt, int s) {
        if constexpr (MODE == 1) {
            const int k0 = kt * BK;
            constexpr int ACH = 2 * BM * 4;    // 16B chunks (hi+lo)
#pragma unroll
            for (int it = 0; it < ACH / 256; ++it) {
                int idx = tid + it * 256;
                int hl = idx / (ACH / 2);
                int cc = idx % (ACH / 2);
                int row = cc >> 2, kc = cc & 3;
                int grow = rowBase + row;
                int sz = (grow < M) ? 16 : 0;
                if (grow >= M) grow = M - 1;
                const __nv_bfloat16* src =
                    (hl ? g_zlo : g_zhi) + (size_t)grow * KDIM + k0 + kc * 8;
                cp_async16(sA + s * A_STAGE + hl * (BM * AST) + row * AST + kc * 16, src, sz);
            }
        }
    };

    auto stageB = [&](int kt, int s) {
        const int k0 = kt * BK;
        constexpr int BCH = 2 * BK * (BN / 8);
#pragma unroll
        for (int it = 0; it < BCH / 256; ++it) {
            int c = tid + it * 256;
            int hl = c / (BCH / 2);
            int cc = c % (BCH / 2);
            int row = cc / (BN / 8), nc = cc % (BN / 8);
            const __nv_bfloat16* src =
                (hl ? Bl : Bh) + (size_t)(k0 + row) * BNF + colBase + nc * 8;
            cp_async16(sB + s * B_STAGE + hl * (BK * BROW) + row * BROW + nc * 16, src, 16);
        }
        asm volatile("cp.async.commit_group;");
    };

    ldgA(0);
    stageA_async(0, 0);
    stageB(0, 0);
    for (int kt = 0; kt < KT; ++kt) {
        const int s = kt & 1;
        stsA(s);
        if (kt + 1 < KT) {
            ldgA(kt + 1);
            stageA_async(kt + 1, s ^ 1);
            stageB(kt + 1, s ^ 1);
            asm volatile("cp.async.wait_group 1;");
        } else {
            asm volatile("cp.async.wait_group 0;");
        }
        __syncthreads();

        const int q = lane >> 3;
#pragma unroll
        for (int ks = 0; ks < 2; ++ks) {
            uint32_t a[MI][2][4];
#pragma unroll
            for (int mi = 0; mi < MI; ++mi) {
                int row  = warpM * (MI * 16) + mi * 16 + (q & 1) * 8 + (lane & 7);
                int colb = (ks * 16 + (q >> 1) * 8) * 2;
#pragma unroll
                for (int hl = 0; hl < 2; ++hl)
                    ldsm_x4(a[mi][hl], sA + s * A_STAGE + hl * (BM * AST) + row * AST + colb);
            }
#pragma unroll
            for (int np = 0; np < NT / 2; ++np) {
                uint32_t bq[2][4];
                int krow = ks * 16 + (q & 1) * 8 + (lane & 7);
                int ncol = warpN * (BN / 4) + np * 16 + (q >> 1) * 8;
#pragma unroll
                for (int hl = 0; hl < 2; ++hl)
                    ldsm_x4_t(bq[hl], sB + s * B_STAGE + hl * (BK * BROW) + krow * BROW + ncol * 2);
#pragma unroll
                for (int half = 0; half < 2; ++half) {
                    uint32_t bh[2] = {bq[0][half * 2], bq[0][half * 2 + 1]};
                    uint32_t bl[2] = {bq[1][half * 2], bq[1][half * 2 + 1]};
                    const int nt = np * 2 + half;
#pragma unroll
                    for (int mi = 0; mi < MI; ++mi) {
                        mma_bf16(acc[mi][nt], a[mi][0], bh);
                        mma_bf16(acc[mi][nt], a[mi][0], bl);
                        mma_bf16(acc[mi][nt], a[mi][1], bh);
                    }
                }
            }
        }
        __syncthreads();
    }

    // epilogue
#pragma unroll
    for (int mi = 0; mi < MI; ++mi)
#pragma unroll
        for (int nt = 0; nt < NT; ++nt) {
            int col = colBase + warpN * (BN / 4) + nt * 8 + t4 * 2;
            int r0  = rowBase + warpM * (MI * 16) + mi * 16 + g;
            if (r0 < M)
                *(float2*)(C + (size_t)r0 * BNF + col) = make_float2(acc[mi][nt][0], acc[mi][nt][1]);
            int r1 = r0 + 8;
            if (r1 < M)
                *(float2*)(C + (size_t)r1 * BNF + col) = make_float2(acc[mi][nt][2], acc[mi][nt][3]);
        }
}

// ---------------------------------------------------------------------------
// Layer-1 gather aggregation (warp per node, C=256) + bias + relu + bf16 split
// ---------------------------------------------------------------------------
__global__ __launch_bounds__(256) void gather_agg1_kernel(const float* __restrict__ b1) {
    int node = (blockIdx.x * blockDim.x + threadIdx.x) >> 5;
    int lane = threadIdx.x & 31;
    if (node >= N_NODES) return;

    const float4* h = g_h1;
    float di = g_dinv[node];
    float ws = di * di;
    size_t rb = (size_t)node * 64;
    float4 a0 = h[rb + lane];
    float4 a1 = h[rb + 32 + lane];
    a0.x *= ws; a0.y *= ws; a0.z *= ws; a0.w *= ws;
    a1.x *= ws; a1.y *= ws; a1.z *= ws; a1.w *= ws;

    int beg = g_eoff[node], end = g_eoff[node + 1];
    int k = beg;
    for (; k + 2 <= end; k += 2) {
        int s0 = g_esrc[k], s1 = g_esrc[k + 1];
        float w0 = g_ew[k], w1 = g_ew[k + 1];
        size_t r0 = (size_t)s0 * 64, r1 = (size_t)s1 * 64;
        float4 v00 = h[r0 + lane], v01 = h[r0 + 32 + lane];
        float4 v10 = h[r1 + lane], v11 = h[r1 + 32 + lane];
        a0.x += v00.x * w0; a0.y += v00.y * w0; a0.z += v00.z * w0; a0.w += v00.w * w0;
        a1.x += v01.x * w0; a1.y += v01.y * w0; a1.z += v01.z * w0; a1.w += v01.w * w0;
        a0.x += v10.x * w1; a0.y += v10.y * w1; a0.z += v10.z * w1; a0.w += v10.w * w1;
        a1.x += v11.x * w1; a1.y += v11.y * w1; a1.z += v11.z * w1; a1.w += v11.w * w1;
    }
    if (k < end) {
        int s0 = g_esrc[k]; float w0 = g_ew[k];
        size_t r0 = (size_t)s0 * 64;
        float4 v00 = h[r0 + lane], v01 = h[r0 + 32 + lane];
        a0.x += v00.x * w0; a0.y += v00.y * w0; a0.z += v00.z * w0; a0.w += v00.w * w0;
        a1.x += v01.x * w0; a1.y += v01.y * w0; a1.z += v01.z * w0; a1.w += v01.w * w0;
    }

    float4 bb0 = ((const float4*)b1)[lane];
    float4 bb1 = ((const float4*)b1)[lane + 32];
    float f0[4] = {fmaxf(a0.x + bb0.x, 0.f), fmaxf(a0.y + bb0.y, 0.f),
                   fmaxf(a0.z + bb0.z, 0.f), fmaxf(a0.w + bb0.w, 0.f)};
    float f1[4] = {fmaxf(a1.x + bb1.x, 0.f), fmaxf(a1.y + bb1.y, 0.f),
                   fmaxf(a1.z + bb1.z, 0.f), fmaxf(a1.w + bb1.w, 0.f)};

    __nv_bfloat162* zh = (__nv_bfloat162*)(g_zhi + (size_t)node * C_HID);
    __nv_bfloat162* zl = (__nv_bfloat162*)(g_zlo + (size_t)node * C_HID);
#pragma unroll
    for (int half = 0; half < 2; ++half) {
        float* f = half ? f1 : f0;
        int idx = 2 * (lane + half * 32);
        __nv_bfloat16 h0 = __float2bfloat16_rn(f[0]);
        __nv_bfloat16 h1v = __float2bfloat16_rn(f[1]);
        __nv_bfloat16 h2v = __float2bfloat16_rn(f[2]);
        __nv_bfloat16 h3 = __float2bfloat16_rn(f[3]);
        zh[idx]     = __nv_bfloat162(h0, h1v);
        zh[idx + 1] = __nv_bfloat162(h2v, h3);
        zl[idx]     = __nv_bfloat162(__float2bfloat16_rn(f[0] - __bfloat162float(h0)),
                                     __float2bfloat16_rn(f[1] - __bfloat162float(h1v)));
        zl[idx + 1] = __nv_bfloat162(__float2bfloat16_rn(f[2] - __bfloat162float(h2v)),
                                     __float2bfloat16_rn(f[3] - __bfloat162float(h3)));
    }
}

// ---------------------------------------------------------------------------
// Layer-2 gather aggregation + bias + row-normalize (warp per node, C=128)
// ---------------------------------------------------------------------------
__global__ __launch_bounds__(256) void gather_agg2_kernel(const float* __restrict__ b2,
                                                          float* __restrict__ out) {
    int node = (blockIdx.x * blockDim.x + threadIdx.x) >> 5;
    int lane = threadIdx.x & 31;
    if (node >= N_NODES) return;

    const float4* h = g_h2;
    float di = g_dinv[node];
    float ws = di * di;
    float4 a = h[(size_t)node * 32 + lane];
    a.x *= ws; a.y *= ws; a.z *= ws; a.w *= ws;

    int beg = g_eoff[node], end = g_eoff[node + 1];
    int k = beg;
    for (; k + 2 <= end; k += 2) {
        int s0 = g_esrc[k], s1 = g_esrc[k + 1];
        float w0 = g_ew[k], w1 = g_ew[k + 1];
        float4 v0 = h[(size_t)s0 * 32 + lane];
        float4 v1 = h[(size_t)s1 * 32 + lane];
        a.x += v0.x * w0; a.y += v0.y * w0; a.z += v0.z * w0; a.w += v0.w * w0;
        a.x += v1.x * w1; a.y += v1.y * w1; a.z += v1.z * w1; a.w += v1.w * w1;
    }
    if (k < end) {
        int s0 = g_esrc[k]; float w0 = g_ew[k];
        float4 v0 = h[(size_t)s0 * 32 + lane];
        a.x += v0.x * w0; a.y += v0.y * w0; a.z += v0.z * w0; a.w += v0.w * w0;
    }

    float4 bb = ((const float4*)b2)[lane];
    a.x += bb.x; a.y += bb.y; a.z += bb.z; a.w += bb.w;
    float s = a.x * a.x + a.y * a.y + a.z * a.z + a.w * a.w;
#pragma unroll
    for (int m = 16; m > 0; m >>= 1) s += __shfl_xor_sync(0xffffffffu, s, m);
    float inv = 1.0f / fmaxf(sqrtf(s), 1e-12f);
    a.x *= inv; a.y *= inv; a.z *= inv; a.w *= inv;
    ((float4*)out)[(size_t)node * 32 + lane] = a;
}

// ---------------------------------------------------------------------------
// Launch
// ---------------------------------------------------------------------------
extern "C" void kernel_launch(void* const* d_in, const int* in_sizes, int n_in,
                              void* d_out, int out_size) {
    const float* x  = (const float*)d_in[0];
    const int*   ei = (const int*)d_in[1];      // int32
    const float* W1 = (const float*)d_in[2];
    const float* b1 = (const float*)d_in[3];
    const float* W2 = (const float*)d_in[4];
    const float* b2 = (const float*)d_in[5];
    float* out = (float*)d_out;

    const int E = in_sizes[1] / 2;
    const int* src = ei;
    const int* dst = ei + E;

    // smem: GEMM1 (MI=2,BN=128): 2*(2*64*80 + 2*32*272) = 55296
    //       GEMM2 (MI=1,BN=128): 2*(2*32*80 + 2*32*272) = 45056
    constexpr int SMEM1 = 2 * (2 * 64 * 80 + 2 * 32 * (128 * 2 + 16));
    constexpr int SMEM2 = 2 * (2 * 32 * 80 + 2 * 32 * (128 * 2 + 16));
    static bool attr_done = false;
    if (!attr_done) {
        cudaFuncSetAttribute((const void*)mma_gemm<2, 128, C_IN, 0>,
                             cudaFuncAttributeMaxDynamicSharedMemorySize, SMEM1);
        cudaFuncSetAttribute((const void*)mma_gemm<1, 128, C_HID, 1>,
                             cudaFuncAttributeMaxDynamicSharedMemorySize, SMEM2);
        attr_done = true;
    }

    // 1) weight splits (single launch)
    split_weights_kernel<<<(W1_N4 + W2_N4 + 255) / 256, 256>>>(W1, W2);

    // 2-3) degree histogram
    zero_deg_kernel<<<(N_NODES + 255) / 256, 256>>>();
    deg_accum_kernel<<<(E + 255) / 256, 256>>>(dst, E);

    // 4) g_h1 = x @ W1  (launch #4 -> ncu profile target)
    {
        dim3 grid((N_NODES + 63) / 64, C_HID / 128);
        mma_gemm<2, 128, C_IN, 0><<<grid, 256, SMEM1>>>(x, N_NODES);
    }

    // 5) scan (+dinv), 6) bucket
    scan_kernel<<<1, SCAN_T>>>();
    bucket_kernel<<<(E + 255) / 256, 256>>>(src, dst, E);

    // 7) layer-1 aggregation + bias + relu + bf16 split (fused)
    gather_agg1_kernel<<<(N_NODES * 32 + 255) / 256, 256>>>(b1);

    // 8) g_h2 = z @ W2
    {
        dim3 grid((N_NODES + 31) / 32, C_OUT / 128);
        mma_gemm<1, 128, C_HID, 1><<<grid, 256, SMEM2>>>(nullptr, N_NODES);
    }

    // 9) layer-2 aggregation + bias + normalize -> out (fused)
    gather_agg2_kernel<<<(N_NODES * 32 + 255) / 256, 256>>>(b2, out);
}

// round 10
// speedup vs baseline: 4.6196x; 1.2213x over previous
#include <cuda_runtime.h>
#include <cuda_bf16.h>
#include <stdint.h>

// Problem constants (from reference setup_inputs)
#define N_NODES 50000
#define C_IN    1536
#define C_HID   256
#define C_OUT   128
#define E_MAX   1600000

// ---------------------------------------------------------------------------
// Device-global scratch (no allocation allowed)
// ---------------------------------------------------------------------------
__device__ float4 g_h1 [N_NODES * C_HID / 4];   // GEMM1 out (f32)
__device__ float4 g_h2 [N_NODES * C_OUT / 4];   // GEMM2 out (f32)
__device__ float  g_dinv[N_NODES];

// CSR-by-dst edge structure (built per launch)
__device__ int    g_deg   [N_NODES];
__device__ int    g_eoff  [N_NODES + 1];
__device__ int    g_cursor[N_NODES];
__device__ int    g_esrc  [E_MAX];
__device__ float  g_ew    [E_MAX];

// bf16 hi/lo splits (K-major weights; z from fused agg1)
__device__ __nv_bfloat16 g_zhi [N_NODES * C_HID];
__device__ __nv_bfloat16 g_zlo [N_NODES * C_HID];
__device__ __nv_bfloat16 g_w1hi[C_IN * C_HID];
__device__ __nv_bfloat16 g_w1lo[C_IN * C_HID];
__device__ __nv_bfloat16 g_w2hi[C_HID * C_OUT];
__device__ __nv_bfloat16 g_w2lo[C_HID * C_OUT];

// ---------------------------------------------------------------------------
// Weight splits: W1 and W2 in ONE launch (f32 -> hi/lo bf16, K-major)
// ---------------------------------------------------------------------------
#define W1_N4 (C_IN * C_HID / 4)    // 98304
#define W2_N4 (C_HID * C_OUT / 4)   // 8192

__global__ void split_weights_kernel(const float* __restrict__ W1,
                                     const float* __restrict__ W2) {
    int i = blockIdx.x * blockDim.x + threadIdx.x;
    if (i >= W1_N4 + W2_N4) return;
    const float4* in;
    __nv_bfloat16 *hi, *lo;
    int j;
    if (i < W1_N4) { in = (const float4*)W1; hi = g_w1hi; lo = g_w1lo; j = i; }
    else           { in = (const float4*)W2; hi = g_w2hi; lo = g_w2lo; j = i - W1_N4; }
    float4 v = in[j];
    float f[4] = {v.x, v.y, v.z, v.w};
    __nv_bfloat16 h[4], l[4];
#pragma unroll
    for (int t = 0; t < 4; ++t) {
        h[t] = __float2bfloat16_rn(f[t]);
        l[t] = __float2bfloat16_rn(f[t] - __bfloat162float(h[t]));
    }
    ((__nv_bfloat162*)hi)[2 * j]     = __nv_bfloat162(h[0], h[1]);
    ((__nv_bfloat162*)hi)[2 * j + 1] = __nv_bfloat162(h[2], h[3]);
    ((__nv_bfloat162*)lo)[2 * j]     = __nv_bfloat162(l[0], l[1]);
    ((__nv_bfloat162*)lo)[2 * j + 1] = __nv_bfloat162(l[2], l[3]);
}

// ---------------------------------------------------------------------------
// degree histogram
// ---------------------------------------------------------------------------
__global__ void zero_deg_kernel() {
    int i = blockIdx.x * blockDim.x + threadIdx.x;
    if (i < N_NODES) g_deg[i] = 0;
}

__global__ void deg_accum_kernel(const int* __restrict__ dst, int E) {
    int i = blockIdx.x * blockDim.x + threadIdx.x;
    if (i < E) {
        unsigned d = (unsigned)dst[i];
        if (d < N_NODES) atomicAdd(&g_deg[d], 1);
    }
}

// ---------------------------------------------------------------------------
// Single-block exclusive scan of g_deg -> g_eoff / g_cursor; also dinv
// ---------------------------------------------------------------------------
#define SCAN_T 1024
__global__ __launch_bounds__(SCAN_T) void scan_kernel() {
    __shared__ int sh[SCAN_T];
    const int tid = threadIdx.x;
    const int PER = (N_NODES + SCAN_T - 1) / SCAN_T;
    const int base = tid * PER;
    int s = 0;
    for (int j = 0; j < PER; ++j) {
        int i = base + j;
        if (i < N_NODES) s += g_deg[i];
    }
    sh[tid] = s;
    __syncthreads();
    for (int off = 1; off < SCAN_T; off <<= 1) {
        int v = (tid >= off) ? sh[tid - off] : 0;
        __syncthreads();
        sh[tid] += v;
        __syncthreads();
    }
    int running = sh[tid] - s;
    for (int j = 0; j < PER; ++j) {
        int i = base + j;
        if (i < N_NODES) {
            int d = g_deg[i];
            g_eoff[i]   = running;
            g_cursor[i] = running;
            g_dinv[i]   = rsqrtf((float)(d + 1));   // +1 self-loop
            running += d;
        }
    }
    if (tid == SCAN_T - 1) g_eoff[N_NODES] = sh[SCAN_T - 1];
}

__global__ void bucket_kernel(const int* __restrict__ src,
                              const int* __restrict__ dst, int E) {
    int e = blockIdx.x * blockDim.x + threadIdx.x;
    if (e >= E) return;
    unsigned s = (unsigned)src[e];
    unsigned d = (unsigned)dst[e];
    if (s >= N_NODES || d >= N_NODES) return;
    int pos = atomicAdd(&g_cursor[d], 1);
    if (pos < E_MAX) {
        g_esrc[pos] = (int)s;
        g_ew[pos]   = g_dinv[s] * g_dinv[d];
    }
}

// ---------------------------------------------------------------------------
// PTX helpers
// ---------------------------------------------------------------------------
__device__ __forceinline__ void mma_bf16(float c[4], const uint32_t a[4],
                                         const uint32_t b[2]) {
    asm volatile(
        "mma.sync.aligned.m16n8k16.row.col.f32.bf16.bf16.f32 "
        "{%0,%1,%2,%3}, {%4,%5,%6,%7}, {%8,%9}, {%0,%1,%2,%3};\n"
        : "+f"(c[0]), "+f"(c[1]), "+f"(c[2]), "+f"(c[3])
        : "r"(a[0]), "r"(a[1]), "r"(a[2]), "r"(a[3]), "r"(b[0]), "r"(b[1]));
}

__device__ __forceinline__ void ldsm_x4(uint32_t r[4], uint32_t addr) {
    asm volatile("ldmatrix.sync.aligned.m8n8.x4.shared.b16 {%0,%1,%2,%3}, [%4];"
                 : "=r"(r[0]), "=r"(r[1]), "=r"(r[2]), "=r"(r[3]) : "r"(addr));
}

__device__ __forceinline__ void ldsm_x4_t(uint32_t r[4], uint32_t addr) {
    asm volatile("ldmatrix.sync.aligned.m8n8.x4.trans.shared.b16 {%0,%1,%2,%3}, [%4];"
                 : "=r"(r[0]), "=r"(r[1]), "=r"(r[2]), "=r"(r[3]) : "r"(addr));
}

__device__ __forceinline__ void cp_async16(uint32_t saddr, const void* g, int srcbytes) {
    asm volatile("cp.async.cg.shared.global [%0], [%1], 16, %2;"
                 :: "r"(saddr), "l"(g), "r"(srcbytes));
}

__device__ __forceinline__ void sts_v2(uint32_t saddr, uint32_t a, uint32_t b) {
    asm volatile("st.shared.v2.b32 [%0], {%1, %2};" :: "r"(saddr), "r"(a), "r"(b));
}

__device__ __forceinline__ uint32_t pack_bf16x2(__nv_bfloat16 a, __nv_bfloat16 b) {
    __nv_bfloat162 p(a, b);
    return *(uint32_t*)&p;
}

// ---------------------------------------------------------------------------
// Unified split-bf16 tensor-core GEMM.  C[M,BNF] = A[M,K] @ B[K,BNF].
// 3-term: Ah*Bh + Ah*Bl + Al*Bh.  Tile: BM = MI*32, BN per CTA, BK=32.
// Inner MMA loop ordered term-outermost: consecutive MMAs hit different
// accumulators (breaks RAW chains); per-accumulator term order unchanged.
// MODE 0: A = X (f32, inline hi/lo split via LDG->STS), B = W1 splits, C = g_h1
// MODE 1: A = z splits (cp.async),                      B = W2 splits, C = g_h2
// ---------------------------------------------------------------------------
template <int MI, int BN, int KDIM, int MODE>
__global__ __launch_bounds__(256, 2) void mma_gemm(const float* __restrict__ X, int M) {
    constexpr int BM   = MI * 32;
    constexpr int BK   = 32;
    constexpr int AST  = 80;                   // A smem row stride (bytes)
    constexpr int BROW = BN * 2 + 16;          // B smem row stride (bytes)
    constexpr int A_STAGE = 2 * BM * AST;      // hi+lo
    constexpr int B_STAGE = 2 * BK * BROW;
    constexpr int NT  = BN / 32;               // n8-tile pairs per warp
    constexpr int KT  = KDIM / BK;
    constexpr int BNF = MODE ? C_OUT : C_HID;  // full width of B rows / C rows

    const __nv_bfloat16* Bh = MODE ? g_w2hi : g_w1hi;
    const __nv_bfloat16* Bl = MODE ? g_w2lo : g_w1lo;
    float*               C  = MODE ? (float*)g_h2 : (float*)g_h1;

    extern __shared__ char smem[];
    uint32_t sA = (uint32_t)__cvta_generic_to_shared(smem);
    uint32_t sB = sA + 2 * A_STAGE;

    const int tid = threadIdx.x, lane = tid & 31, warp = tid >> 5;
    const int warpM = warp & 1, warpN = warp >> 1;
    const int g = lane >> 2, t4 = lane & 3;
    const int rowBase = blockIdx.x * BM;
    const int colBase = blockIdx.y * BN;

    float acc[MI][NT][4] = {};

    constexpr int AC = (BM * 8) / 256;         // 2 for BM=64, 1 for BM=32
    float4 areg[AC > 0 ? AC : 1];

    auto ldgA = [&](int kt) {
        if constexpr (MODE == 0) {
            const int k0 = kt * BK;
#pragma unroll
            for (int it = 0; it < AC; ++it) {
                int idx = tid + it * 256;
                int row = idx >> 3;
                int c4  = idx & 7;
                int grow = rowBase + row;
                if (grow >= M) grow = M - 1;
                areg[it] = *(const float4*)(X + (size_t)grow * KDIM + k0 + c4 * 4);
            }
        }
    };

    auto stsA = [&](int s) {
        if constexpr (MODE == 0) {
#pragma unroll
            for (int it = 0; it < AC; ++it) {
                int idx = tid + it * 256;
                int row = idx >> 3;
                int c4  = idx & 7;
                float f[4] = {areg[it].x, areg[it].y, areg[it].z, areg[it].w};
                __nv_bfloat16 h[4], l[4];
#pragma unroll
                for (int j = 0; j < 4; ++j) {
                    h[j] = __float2bfloat16_rn(f[j]);
                    l[j] = __float2bfloat16_rn(f[j] - __bfloat162float(h[j]));
                }
                uint32_t base = sA + s * A_STAGE + row * AST + c4 * 8;
                sts_v2(base,            pack_bf16x2(h[0], h[1]), pack_bf16x2(h[2], h[3]));
                sts_v2(base + BM * AST, pack_bf16x2(l[0], l[1]), pack_bf16x2(l[2], l[3]));
            }
        }
    };

    auto stageA_async = [&](int kt, int s) {
        if constexpr (MODE == 1) {
            const int k0 = kt * BK;
            constexpr int ACH = 2 * BM * 4;
#pragma unroll
            for (int it = 0; it < ACH / 256; ++it) {
                int idx = tid + it * 256;
                int hl = idx / (ACH / 2);
                int cc = idx % (ACH / 2);
                int row = cc >> 2, kc = cc & 3;
                int grow = rowBase + row;
                int sz = (grow < M) ? 16 : 0;
                if (grow >= M) grow = M - 1;
                const __nv_bfloat16* src =
                    (hl ? g_zlo : g_zhi) + (size_t)grow * KDIM + k0 + kc * 8;
                cp_async16(sA + s * A_STAGE + hl * (BM * AST) + row * AST + kc * 16, src, sz);
            }
        }
    };

    auto stageB = [&](int kt, int s) {
        const int k0 = kt * BK;
        constexpr int BCH = 2 * BK * (BN / 8);
#pragma unroll
        for (int it = 0; it < BCH / 256; ++it) {
            int c = tid + it * 256;
            int hl = c / (BCH / 2);
            int cc = c % (BCH / 2);
            int row = cc / (BN / 8), nc = cc % (BN / 8);
            const __nv_bfloat16* src =
                (hl ? Bl : Bh) + (size_t)(k0 + row) * BNF + colBase + nc * 8;
            cp_async16(sB + s * B_STAGE + hl * (BK * BROW) + row * BROW + nc * 16, src, 16);
        }
        asm volatile("cp.async.commit_group;");
    };

    ldgA(0);
    stageA_async(0, 0);
    stageB(0, 0);
    for (int kt = 0; kt < KT; ++kt) {
        const int s = kt & 1;
        stsA(s);
        if (kt + 1 < KT) {
            ldgA(kt + 1);
            stageA_async(kt + 1, s ^ 1);
            stageB(kt + 1, s ^ 1);
            asm volatile("cp.async.wait_group 1;");
        } else {
            asm volatile("cp.async.wait_group 0;");
        }
        __syncthreads();

        const int q = lane >> 3;
#pragma unroll
        for (int ks = 0; ks < 2; ++ks) {
            uint32_t a[MI][2][4];
#pragma unroll
            for (int mi = 0; mi < MI; ++mi) {
                int row  = warpM * (MI * 16) + mi * 16 + (q & 1) * 8 + (lane & 7);
                int colb = (ks * 16 + (q >> 1) * 8) * 2;
#pragma unroll
                for (int hl = 0; hl < 2; ++hl)
                    ldsm_x4(a[mi][hl], sA + s * A_STAGE + hl * (BM * AST) + row * AST + colb);
            }
#pragma unroll
            for (int np = 0; np < NT / 2; ++np) {
                uint32_t bq[2][4];
                int krow = ks * 16 + (q & 1) * 8 + (lane & 7);
                int ncol = warpN * (BN / 4) + np * 16 + (q >> 1) * 8;
#pragma unroll
                for (int hl = 0; hl < 2; ++hl)
                    ldsm_x4_t(bq[hl], sB + s * B_STAGE + hl * (BK * BROW) + krow * BROW + ncol * 2);
                // term-outermost: consecutive MMAs hit different accumulators;
                // per-acc order stays hh -> hl -> lh (bitwise identical result)
#pragma unroll
                for (int term = 0; term < 3; ++term) {
                    const int ahl = (term == 2) ? 1 : 0;
                    const int bhl = (term == 1) ? 1 : 0;
#pragma unroll
                    for (int half = 0; half < 2; ++half) {
                        uint32_t bb[2] = {bq[bhl][half * 2], bq[bhl][half * 2 + 1]};
                        const int nt = np * 2 + half;
#pragma unroll
                        for (int mi = 0; mi < MI; ++mi)
                            mma_bf16(acc[mi][nt], a[mi][ahl], bb);
                    }
                }
            }
        }
        __syncthreads();
    }

    // epilogue
#pragma unroll
    for (int mi = 0; mi < MI; ++mi)
#pragma unroll
        for (int nt = 0; nt < NT; ++nt) {
            int col = colBase + warpN * (BN / 4) + nt * 8 + t4 * 2;
            int r0  = rowBase + warpM * (MI * 16) + mi * 16 + g;
            if (r0 < M)
                *(float2*)(C + (size_t)r0 * BNF + col) = make_float2(acc[mi][nt][0], acc[mi][nt][1]);
            int r1 = r0 + 8;
            if (r1 < M)
                *(float2*)(C + (size_t)r1 * BNF + col) = make_float2(acc[mi][nt][2], acc[mi][nt][3]);
        }
}

// ---------------------------------------------------------------------------
// Layer-1 gather aggregation (warp per node, C=256) + bias + relu + bf16 split
// ---------------------------------------------------------------------------
__global__ __launch_bounds__(256) void gather_agg1_kernel(const float* __restrict__ b1) {
    int node = (blockIdx.x * blockDim.x + threadIdx.x) >> 5;
    int lane = threadIdx.x & 31;
    if (node >= N_NODES) return;

    const float4* h = g_h1;
    float di = g_dinv[node];
    float ws = di * di;
    size_t rb = (size_t)node * 64;
    float4 a0 = h[rb + lane];
    float4 a1 = h[rb + 32 + lane];
    a0.x *= ws; a0.y *= ws; a0.z *= ws; a0.w *= ws;
    a1.x *= ws; a1.y *= ws; a1.z *= ws; a1.w *= ws;

    int beg = g_eoff[node], end = g_eoff[node + 1];
    int k = beg;
    for (; k + 2 <= end; k += 2) {
        int s0 = g_esrc[k], s1 = g_esrc[k + 1];
        float w0 = g_ew[k], w1 = g_ew[k + 1];
        size_t r0 = (size_t)s0 * 64, r1 = (size_t)s1 * 64;
        float4 v00 = h[r0 + lane], v01 = h[r0 + 32 + lane];
        float4 v10 = h[r1 + lane], v11 = h[r1 + 32 + lane];
        a0.x += v00.x * w0; a0.y += v00.y * w0; a0.z += v00.z * w0; a0.w += v00.w * w0;
        a1.x += v01.x * w0; a1.y += v01.y * w0; a1.z += v01.z * w0; a1.w += v01.w * w0;
        a0.x += v10.x * w1; a0.y += v10.y * w1; a0.z += v10.z * w1; a0.w += v10.w * w1;
        a1.x += v11.x * w1; a1.y += v11.y * w1; a1.z += v11.z * w1; a1.w += v11.w * w1;
    }
    if (k < end) {
        int s0 = g_esrc[k]; float w0 = g_ew[k];
        size_t r0 = (size_t)s0 * 64;
        float4 v00 = h[r0 + lane], v01 = h[r0 + 32 + lane];
        a0.x += v00.x * w0; a0.y += v00.y * w0; a0.z += v00.z * w0; a0.w += v00.w * w0;
        a1.x += v01.x * w0; a1.y += v01.y * w0; a1.z += v01.z * w0; a1.w += v01.w * w0;
    }

    float4 bb0 = ((const float4*)b1)[lane];
    float4 bb1 = ((const float4*)b1)[lane + 32];
    float f0[4] = {fmaxf(a0.x + bb0.x, 0.f), fmaxf(a0.y + bb0.y, 0.f),
                   fmaxf(a0.z + bb0.z, 0.f), fmaxf(a0.w + bb0.w, 0.f)};
    float f1[4] = {fmaxf(a1.x + bb1.x, 0.f), fmaxf(a1.y + bb1.y, 0.f),
                   fmaxf(a1.z + bb1.z, 0.f), fmaxf(a1.w + bb1.w, 0.f)};

    __nv_bfloat162* zh = (__nv_bfloat162*)(g_zhi + (size_t)node * C_HID);
    __nv_bfloat162* zl = (__nv_bfloat162*)(g_zlo + (size_t)node * C_HID);
#pragma unroll
    for (int half = 0; half < 2; ++half) {
        float* f = half ? f1 : f0;
        int idx = 2 * (lane + half * 32);
        __nv_bfloat16 h0 = __float2bfloat16_rn(f[0]);
        __nv_bfloat16 h1v = __float2bfloat16_rn(f[1]);
        __nv_bfloat16 h2v = __float2bfloat16_rn(f[2]);
        __nv_bfloat16 h3 = __float2bfloat16_rn(f[3]);
        zh[idx]     = __nv_bfloat162(h0, h1v);
        zh[idx + 1] = __nv_bfloat162(h2v, h3);
        zl[idx]     = __nv_bfloat162(__float2bfloat16_rn(f[0] - __bfloat162float(h0)),
                                     __float2bfloat16_rn(f[1] - __bfloat162float(h1v)));
        zl[idx + 1] = __nv_bfloat162(__float2bfloat16_rn(f[2] - __bfloat162float(h2v)),
                                     __float2bfloat16_rn(f[3] - __bfloat162float(h3)));
    }
}

// ---------------------------------------------------------------------------
// Layer-2 gather aggregation + bias + row-normalize (warp per node, C=128)
// ---------------------------------------------------------------------------
__global__ __launch_bounds__(256) void gather_agg2_kernel(const float* __restrict__ b2,
                                                          float* __restrict__ out) {
    int node = (blockIdx.x * blockDim.x + threadIdx.x) >> 5;
    int lane = threadIdx.x & 31;
    if (node >= N_NODES) return;

    const float4* h = g_h2;
    float di = g_dinv[node];
    float ws = di * di;
    float4 a = h[(size_t)node * 32 + lane];
    a.x *= ws; a.y *= ws; a.z *= ws; a.w *= ws;

    int beg = g_eoff[node], end = g_eoff[node + 1];
    int k = beg;
    for (; k + 2 <= end; k += 2) {
        int s0 = g_esrc[k], s1 = g_esrc[k + 1];
        float w0 = g_ew[k], w1 = g_ew[k + 1];
        float4 v0 = h[(size_t)s0 * 32 + lane];
        float4 v1 = h[(size_t)s1 * 32 + lane];
        a.x += v0.x * w0; a.y += v0.y * w0; a.z += v0.z * w0; a.w += v0.w * w0;
        a.x += v1.x * w1; a.y += v1.y * w1; a.z += v1.z * w1; a.w += v1.w * w1;
    }
    if (k < end) {
        int s0 = g_esrc[k]; float w0 = g_ew[k];
        float4 v0 = h[(size_t)s0 * 32 + lane];
        a.x += v0.x * w0; a.y += v0.y * w0; a.z += v0.z * w0; a.w += v0.w * w0;
    }

    float4 bb = ((const float4*)b2)[lane];
    a.x += bb.x; a.y += bb.y; a.z += bb.z; a.w += bb.w;
    float s = a.x * a.x + a.y * a.y + a.z * a.z + a.w * a.w;
#pragma unroll
    for (int m = 16; m > 0; m >>= 1) s += __shfl_xor_sync(0xffffffffu, s, m);
    float inv = 1.0f / fmaxf(sqrtf(s), 1e-12f);
    a.x *= inv; a.y *= inv; a.z *= inv; a.w *= inv;
    ((float4*)out)[(size_t)node * 32 + lane] = a;
}

// ---------------------------------------------------------------------------
// Launch: CSR build overlapped with weight-split + GEMM1 on a second stream.
// Streams/events are created once on the first (uncaptured) call.
// ---------------------------------------------------------------------------
extern "C" void kernel_launch(void* const* d_in, const int* in_sizes, int n_in,
                              void* d_out, int out_size) {
    const float* x  = (const float*)d_in[0];
    const int*   ei = (const int*)d_in[1];      // int32
    const float* W1 = (const float*)d_in[2];
    const float* b1 = (const float*)d_in[3];
    const float* W2 = (const float*)d_in[4];
    const float* b2 = (const float*)d_in[5];
    float* out = (float*)d_out;

    const int E = in_sizes[1] / 2;
    const int* src = ei;
    const int* dst = ei + E;

    constexpr int SMEM1 = 2 * (2 * 64 * 80 + 2 * 32 * (128 * 2 + 16));  // 55296
    constexpr int SMEM2 = 2 * (2 * 32 * 80 + 2 * 32 * (128 * 2 + 16)); // 45056

    static cudaStream_t s2 = nullptr;
    static cudaEvent_t  evF = nullptr, evJ = nullptr;
    static bool init_done = false;
    if (!init_done) {
        cudaFuncSetAttribute((const void*)mma_gemm<2, 128, C_IN, 0>,
                             cudaFuncAttributeMaxDynamicSharedMemorySize, SMEM1);
        cudaFuncSetAttribute((const void*)mma_gemm<1, 128, C_HID, 1>,
                             cudaFuncAttributeMaxDynamicSharedMemorySize, SMEM2);
        cudaStreamCreateWithFlags(&s2, cudaStreamNonBlocking);
        cudaEventCreateWithFlags(&evF, cudaEventDisableTiming);
        cudaEventCreateWithFlags(&evJ, cudaEventDisableTiming);
        init_done = true;
    }

    // fork: CSR build chain on s2 (disjoint buffers from GEMM1 path)
    cudaEventRecord(evF, 0);
    cudaStreamWaitEvent(s2, evF, 0);
    zero_deg_kernel<<<(N_NODES + 255) / 256, 256, 0, s2>>>();
    deg_accum_kernel<<<(E + 255) / 256, 256, 0, s2>>>(dst, E);
    scan_kernel<<<1, SCAN_T, 0, s2>>>();
    bucket_kernel<<<(E + 255) / 256, 256, 0, s2>>>(src, dst, E);
    cudaEventRecord(evJ, s2);

    // main stream: weight splits + GEMM1 (concurrent with CSR build)
    split_weights_kernel<<<(W1_N4 + W2_N4 + 255) / 256, 256>>>(W1, W2);
    {
        dim3 grid((N_NODES + 63) / 64, C_HID / 128);
        mma_gemm<2, 128, C_IN, 0><<<grid, 256, SMEM1>>>(x, N_NODES);
    }

    // join: agg1 needs both g_h1 (main) and CSR (s2)
    cudaStreamWaitEvent(0, evJ, 0);

    gather_agg1_kernel<<<(N_NODES * 32 + 255) / 256, 256>>>(b1);
    {
        dim3 grid((N_NODES + 31) / 32, C_OUT / 128);
        mma_gemm<1, 128, C_HID, 1><<<grid, 256, SMEM2>>>(nullptr, N_NODES);
    }
    gather_agg2_kernel<<<(N_NODES * 32 + 255) / 256, 256>>>(b2, out);
}